// round 3
// baseline (speedup 1.0000x reference)
#include <cuda_runtime.h>
#include <math.h>
#include <stdint.h>

// Problem constants
#define BB 128
#define NN 49
#define CC 2048
#define DD 512
#define EE 512
#define VV 10000
#define TT 20
#define XD1 1024       // x = [vg | we]
#define XDIM 1536      // x plus h
#define GDIM 2560      // 4D gates + D gate-linear
#define KSINF (1 << 30)

// ---------------- device scratch ----------------
__device__ __align__(16) float g_mean[BB * CC];
__device__ __align__(16) float g_vghm[BB * 1536];
__device__ __align__(16) float g_Vf[BB * NN * DD];
__device__ __align__(16) float g_zbase[BB * NN * NN];
__device__ __align__(16) float g_xall[TT * BB * XD1];
__device__ __align__(16) float g_Wcat[GDIM * XDIM];
__device__ __align__(16) float g_bcat[GDIM];
__device__ __align__(16) float g_Wbhm[1536 * CC];
__device__ __align__(16) float g_bbhm[1536];
__device__ __align__(16) float g_preact[BB * GDIM];
__device__ __align__(16) float g_h[2][BB * DD];
__device__ __align__(16) float g_m[2][BB * DD];
__device__ __align__(16) float g_u[BB * DD];
__device__ __align__(16) float g_Hb[BB * DD];
__device__ __align__(16) float g_sb[BB * DD];
__device__ __align__(16) float g_t1[BB * DD];
__device__ __align__(16) float g_o512[BB * DD];

__device__ __forceinline__ float sigf(float x) { return 1.0f / (1.0f + expf(-x)); }

__device__ __forceinline__ uint32_t to_tf32(float f) {
    uint32_t r; asm("cvt.rna.tf32.f32 %0, %1;" : "=r"(r) : "f"(f)); return r;
}

__device__ __forceinline__ void mma8(float* c, const uint4 a, const uint2 b) {
    asm volatile("mma.sync.aligned.m16n8k8.row.col.f32.tf32.tf32.f32 "
        "{%0,%1,%2,%3}, {%4,%5,%6,%7}, {%8,%9}, {%0,%1,%2,%3};"
        : "+f"(c[0]), "+f"(c[1]), "+f"(c[2]), "+f"(c[3])
        : "r"(a.x), "r"(a.y), "r"(a.z), "r"(a.w), "r"(b.x), "r"(b.y));
}

// ============ tf32 tensor-core GEMM body ============
// C[m,n] = act( sum_k A[m,k] * W[n,k] + bias[n] )
// Block tile 64x64, BK=32, 128 threads (4 warps, 2x2 warp grid of 32x32).
// A rows assumed valid (M multiple of 64 at call sites); W rows masked vs N.
// A is split at ksplit: cols >= ksplit come from A2 (for [x|h] concat).
template <int ACT>   // 0 none, 1 relu, 2 tanh
__device__ __forceinline__ void gemm_tf32_body(
    const float* __restrict__ A, int lda,
    const float* __restrict__ A2, int lda2, int ksplit,
    const float* __restrict__ W, int ldw,
    const float* __restrict__ bias,
    float* __restrict__ C, long long ldc, int N, int K)
{
    // permuted fragment smem: sA[kt][mt][128], sB[kt][nt][64]
    __shared__ uint32_t sA[4 * 4 * 128];
    __shared__ uint32_t sB[4 * 8 * 64];

    const int tid = threadIdx.x;
    const int crow = tid >> 1;           // 0..63
    const int cbase = (tid & 1) * 16;    // 0 or 16
    const int m0 = blockIdx.y * 64, n0 = blockIdx.x * 64;
    const int lane = tid & 31, w = tid >> 5;
    const int wm = (w >> 1) * 32, wn = (w & 1) * 32;

    const int arow = m0 + crow;
    const int wrow = n0 + crow;
    const bool wvalid = (wrow < N);

    const int r16 = crow & 15, mt = crow >> 4;
    const int nt = crow >> 3;
    const int rlA = (crow & 7) * 16;     // lane*4 base for A scatter
    const int rlB = (crow & 7) * 8;      // lane*2 base for B scatter

    float acc[2][4][4];
#pragma unroll
    for (int i = 0; i < 2; i++)
#pragma unroll
        for (int j = 0; j < 4; j++)
#pragma unroll
            for (int u = 0; u < 4; u++) acc[i][j][u] = 0.f;

    for (int k0 = 0; k0 < K; k0 += 32) {
        __syncthreads();
        // ---- A copy + tf32 convert + fragment scatter ----
#pragma unroll
        for (int e = 0; e < 4; e++) {
            const int c = cbase + e * 4;
            const int gk = k0 + c;
            float4 v;
            if (gk < ksplit) v = *reinterpret_cast<const float4*>(A + (size_t)arow * lda + gk);
            else             v = *reinterpret_cast<const float4*>(A2 + (size_t)arow * lda2 + (gk - ksplit));
            const int kt = (c >> 3);
            const int reg = (r16 >> 3) + 2 * ((c & 7) >> 2);
            uint32_t* base = &sA[(kt * 4 + mt) * 128 + rlA + reg];
            base[0]  = to_tf32(v.x);
            base[4]  = to_tf32(v.y);
            base[8]  = to_tf32(v.z);
            base[12] = to_tf32(v.w);
        }
        // ---- B (W) copy ----
#pragma unroll
        for (int e = 0; e < 4; e++) {
            const int c = cbase + e * 4;
            const int gk = k0 + c;
            float4 v = make_float4(0.f, 0.f, 0.f, 0.f);
            if (wvalid) v = *reinterpret_cast<const float4*>(W + (size_t)wrow * ldw + gk);
            const int kt = (c >> 3);
            const int reg = (c & 7) >> 2;
            uint32_t* base = &sB[(kt * 8 + nt) * 64 + rlB + reg];
            base[0] = to_tf32(v.x);
            base[2] = to_tf32(v.y);
            base[4] = to_tf32(v.z);
            base[6] = to_tf32(v.w);
        }
        __syncthreads();
        // ---- compute ----
#pragma unroll
        for (int kt = 0; kt < 4; kt++) {
            uint4 af[2];
            af[0] = *reinterpret_cast<const uint4*>(&sA[(kt * 4 + (wm >> 4) + 0) * 128 + lane * 4]);
            af[1] = *reinterpret_cast<const uint4*>(&sA[(kt * 4 + (wm >> 4) + 1) * 128 + lane * 4]);
            uint2 bf[4];
#pragma unroll
            for (int j = 0; j < 4; j++)
                bf[j] = *reinterpret_cast<const uint2*>(&sB[(kt * 8 + (wn >> 3) + j) * 64 + lane * 2]);
#pragma unroll
            for (int i = 0; i < 2; i++)
#pragma unroll
                for (int j = 0; j < 4; j++)
                    mma8(acc[i][j], af[i], bf[j]);
        }
    }

    // ---- epilogue ----
    const int g = lane >> 2, q = lane & 3;
#pragma unroll
    for (int i = 0; i < 2; i++) {
        const int r0 = m0 + wm + i * 16 + g;
#pragma unroll
        for (int j = 0; j < 4; j++) {
            const int col = n0 + wn + j * 8 + q * 2;
            float b0v = 0.f, b1v = 0.f;
            if (bias) {
                if (col < N)     b0v = bias[col];
                if (col + 1 < N) b1v = bias[col + 1];
            }
            float v00 = acc[i][j][0] + b0v, v01 = acc[i][j][1] + b1v;
            float v10 = acc[i][j][2] + b0v, v11 = acc[i][j][3] + b1v;
            if (ACT == 1) {
                v00 = fmaxf(v00, 0.f); v01 = fmaxf(v01, 0.f);
                v10 = fmaxf(v10, 0.f); v11 = fmaxf(v11, 0.f);
            } else if (ACT == 2) {
                v00 = tanhf(v00); v01 = tanhf(v01);
                v10 = tanhf(v10); v11 = tanhf(v11);
            }
            if (col < N) {
                C[(size_t)r0 * ldc + col] = v00;
                C[(size_t)(r0 + 8) * ldc + col] = v10;
            }
            if (col + 1 < N) {
                C[(size_t)r0 * ldc + col + 1] = v01;
                C[(size_t)(r0 + 8) * ldc + col + 1] = v11;
            }
        }
    }
}

template <int ACT>
__global__ void tf32_gemm(const float* __restrict__ A, int lda,
                          const float* __restrict__ A2, int lda2, int ksplit,
                          const float* __restrict__ W, int ldw,
                          const float* __restrict__ bias,
                          float* __restrict__ C, long long ldc, int N, int K)
{
    gemm_tf32_body<ACT>(A, lda, A2, lda2, ksplit, W, ldw, bias, C, ldc, N, K);
}

// combined H and s GEMMs: blockIdx.z selects
__global__ void hs_tf32(const float* __restrict__ h2, const float* __restrict__ u,
                        const float* __restrict__ WH, const float* __restrict__ Wc,
                        const float* __restrict__ bc)
{
    if (blockIdx.z == 0)
        gemm_tf32_body<1>(h2, DD, h2, DD, KSINF, WH, DD, nullptr, g_Hb, DD, DD, DD);
    else
        gemm_tf32_body<1>(u, DD, u, DD, KSINF, Wc, DD, bc, g_sb, DD, DD, DD);
}

// ---------------- small kernels ----------------
__global__ void mean_kernel(const float* __restrict__ img)
{
    int idx = blockIdx.x * blockDim.x + threadIdx.x;
    if (idx >= BB * CC) return;
    int b = idx / CC, c = idx % CC;
    const float* p = img + (size_t)b * NN * CC + c;
    float s = 0.f;
#pragma unroll 7
    for (int n = 0; n < NN; n++) s += p[(size_t)n * CC];
    g_mean[idx] = s * (1.0f / NN);
}

__global__ void hm_init_kernel()
{
    int idx = blockIdx.x * blockDim.x + threadIdx.x;
    if (idx >= BB * DD) return;
    int b = idx >> 9, d = idx & 511;
    g_h[0][idx] = g_vghm[b * 1536 + 512 + d];
    g_m[0][idx] = g_vghm[b * 1536 + 1024 + d];
}

__global__ void xall_init_kernel(const float* __restrict__ emb, const int* __restrict__ target)
{
    int idx = blockIdx.x * blockDim.x + threadIdx.x;
    if (idx >= TT * BB * XD1) return;
    int j = idx % XD1;
    int tb = idx / XD1;
    int b = tb % BB;
    int t = tb / BB;
    float v;
    if (j < 512) v = g_vghm[b * 1536 + j];          // vg
    else if (t == 0) v = 0.f;
    else {
        int tok = target[b * TT + t - 1];
        v = emb[(size_t)tok * EE + (j - 512)];
    }
    g_xall[((size_t)t * BB + b) * XD1 + j] = v;
}

__global__ void build_wcat_kernel(const float* __restrict__ Wih, const float* __restrict__ Whh,
                                  const float* __restrict__ Wx, const float* __restrict__ Wh2,
                                  const float* __restrict__ bih, const float* __restrict__ bhh)
{
    int idx = blockIdx.x * blockDim.x + threadIdx.x;
    if (idx >= GDIM * XDIM) return;
    int r = idx / XDIM, c = idx % XDIM;
    float v;
    if (r < 2048) v = (c < 1024) ? Wih[(size_t)r * 1024 + c] : Whh[(size_t)r * 512 + (c - 1024)];
    else {
        int r2 = r - 2048;
        v = (c < 1024) ? Wx[(size_t)r2 * 1024 + c] : Wh2[(size_t)r2 * 512 + (c - 1024)];
    }
    g_Wcat[idx] = v;
    if (c == 0) g_bcat[r] = (r < 2048) ? (bih[r] + bhh[r]) : 0.f;
}

// LSTM nonlinearity (preact already includes bias from GEMM)
__global__ void lstm_elem_kernel(int cur, int nxt)
{
    int idx = blockIdx.x * blockDim.x + threadIdx.x;
    if (idx >= BB * DD) return;
    int b = idx >> 9, d = idx & 511;
    const float* p = g_preact + (size_t)b * GDIM;
    float gi = p[d], gf = p[512 + d], gg = p[1024 + d], go = p[1536 + d], gl = p[2048 + d];
    float m2 = sigf(gf) * g_m[cur][idx] + sigf(gi) * tanhf(gg);
    float tm2 = tanhf(m2);
    g_m[nxt][idx] = m2;
    g_h[nxt][idx] = sigf(go) * tm2;
    g_u[idx] = sigf(gl) * tm2;
}

// fused attention: gH, sWs, z, z2, softmax(50), attn out, ctx, t1=H+ctx
__global__ void attn_fused_kernel(const float* __restrict__ Wg, const float* __restrict__ Wsm,
                                  const float* __restrict__ wh,
                                  float* __restrict__ attn_out, int t)
{
    int b = blockIdx.x;
    __shared__ float sH[512], sS[512];
    __shared__ float gHs[49], sWss[49], zsh[50], wsh[49];
    int tid = threadIdx.x;  // 256
    for (int j = tid; j < 512; j += 256) {
        sH[j] = g_Hb[b * 512 + j];
        sS[j] = g_sb[b * 512 + j];
    }
    if (tid < 49) wsh[tid] = wh[tid];
    __syncthreads();

    int w = tid >> 5, lane = tid & 31;
    for (int n = w; n < 49; n += 8) {
        float a = 0.f, c = 0.f;
        const float* wg = Wg + (size_t)n * 512;
        const float* ws = Wsm + (size_t)n * 512;
        for (int d = lane; d < 512; d += 32) {
            a = fmaf(sH[d], wg[d], a);
            c = fmaf(sS[d], ws[d], c);
        }
#pragma unroll
        for (int off = 16; off; off >>= 1) {
            a += __shfl_down_sync(0xffffffffu, a, off);
            c += __shfl_down_sync(0xffffffffu, c, off);
        }
        if (lane == 0) { gHs[n] = a; sWss[n] = c; }
    }
    __syncthreads();

    if (tid < 49) {
        const float* zb = g_zbase + ((size_t)b * 49 + tid) * 49;
        float acc = 0.f;
#pragma unroll 7
        for (int k = 0; k < 49; k++) acc += tanhf(zb[k] + gHs[k]) * wsh[k];
        zsh[tid] = acc;
    } else if (tid == 49) {
        float acc = 0.f;
#pragma unroll 7
        for (int k = 0; k < 49; k++) acc += tanhf(sWss[k] + gHs[k]) * wsh[k];
        zsh[49] = acc;
    }
    __syncthreads();

    if (tid == 0) {
        float mx = -1e30f;
        for (int i = 0; i < 50; i++) mx = fmaxf(mx, zsh[i]);
        float sum = 0.f;
        for (int i = 0; i < 50; i++) { zsh[i] = expf(zsh[i] - mx); sum += zsh[i]; }
        float inv = 1.f / sum;
        for (int i = 0; i < 50; i++) zsh[i] *= inv;
    }
    __syncthreads();

    if (tid < 49) attn_out[((size_t)b * TT + t) * 49 + tid] = zsh[tid];

    float a50 = zsh[49];
    for (int d = tid; d < 512; d += 256) {
        float acc = a50 * sS[d];
#pragma unroll 7
        for (int n = 0; n < 49; n++)
            acc = fmaf(zsh[n], g_Vf[((size_t)b * 49 + n) * 512 + d], acc);
        g_t1[b * 512 + d] = sH[d] + acc;
    }
}

__global__ void log_softmax_kernel(float* __restrict__ logits)
{
    int row = blockIdx.x;  // B*T rows
    float* x = logits + (size_t)row * VV;
    __shared__ float red[256];
    int tid = threadIdx.x;
    float mx = -1e30f;
    for (int i = tid; i < VV; i += 256) mx = fmaxf(mx, x[i]);
    red[tid] = mx; __syncthreads();
    for (int s = 128; s; s >>= 1) { if (tid < s) red[tid] = fmaxf(red[tid], red[tid + s]); __syncthreads(); }
    mx = red[0];
    __syncthreads();
    float sum = 0.f;
    for (int i = tid; i < VV; i += 256) sum += expf(x[i] - mx);
    red[tid] = sum; __syncthreads();
    for (int s = 128; s; s >>= 1) { if (tid < s) red[tid] += red[tid + s]; __syncthreads(); }
    float lse = mx + logf(red[0]);
    for (int i = tid; i < VV; i += 256) x[i] -= lse;
}

// ---------------- host ----------------
static inline dim3 tgrid(int M, int N) { return dim3((N + 63) / 64, (M + 63) / 64); }

extern "C" void kernel_launch(void* const* d_in, const int* in_sizes, int n_in,
                              void* d_out, int out_size)
{
    const float* img    = (const float*)d_in[0];
    const int*   target = (const int*)d_in[1];
    const float* emb    = (const float*)d_in[2];
    const float* Wa  = (const float*)d_in[3];  const float* ba  = (const float*)d_in[4];
    const float* Wb  = (const float*)d_in[5];  const float* bb  = (const float*)d_in[6];
    const float* Whi = (const float*)d_in[7];  const float* bhi = (const float*)d_in[8];
    const float* Wmi = (const float*)d_in[9];  const float* bmi = (const float*)d_in[10];
    const float* Wih = (const float*)d_in[11]; const float* bih = (const float*)d_in[12];
    const float* Whh = (const float*)d_in[13]; const float* bhh = (const float*)d_in[14];
    const float* Wv  = (const float*)d_in[15];
    const float* Wg  = (const float*)d_in[16];
    const float* wh  = (const float*)d_in[17];
    const float* WH  = (const float*)d_in[18];
    const float* Wx  = (const float*)d_in[19];
    const float* Wh2 = (const float*)d_in[20];
    const float* Wsm = (const float*)d_in[21];
    const float* Wc  = (const float*)d_in[22]; const float* bc  = (const float*)d_in[23];
    const float* Wfc = (const float*)d_in[24]; const float* bfc = (const float*)d_in[25];
    const float* Wp  = (const float*)d_in[26]; const float* bp  = (const float*)d_in[27];

    float* out_logits = (float*)d_out;                               // [B,T,VOC]
    float* out_attn   = (float*)d_out + (size_t)BB * TT * VV;        // [B,T,N]

    float *p_mean, *p_vghm, *p_Vf, *p_xall, *p_Wbhm, *p_bbhm, *p_Wcat, *p_bcat;
    float *p_preact, *p_h, *p_u, *p_t1, *p_o512, *p_zbase;
    cudaGetSymbolAddress((void**)&p_mean,  g_mean);
    cudaGetSymbolAddress((void**)&p_vghm,  g_vghm);
    cudaGetSymbolAddress((void**)&p_Vf,    g_Vf);
    cudaGetSymbolAddress((void**)&p_zbase, g_zbase);
    cudaGetSymbolAddress((void**)&p_xall,  g_xall);
    cudaGetSymbolAddress((void**)&p_Wbhm,  g_Wbhm);
    cudaGetSymbolAddress((void**)&p_bbhm,  g_bbhm);
    cudaGetSymbolAddress((void**)&p_Wcat,  g_Wcat);
    cudaGetSymbolAddress((void**)&p_bcat,  g_bcat);
    cudaGetSymbolAddress((void**)&p_preact,g_preact);
    cudaGetSymbolAddress((void**)&p_h,     g_h);
    cudaGetSymbolAddress((void**)&p_u,     g_u);
    cudaGetSymbolAddress((void**)&p_t1,    g_t1);
    cudaGetSymbolAddress((void**)&p_o512,  g_o512);

    // ---- precompute ----
    const size_t WSZ = (size_t)DD * CC * sizeof(float);
    cudaMemcpyAsync(p_Wbhm,             Wb,  WSZ, cudaMemcpyDeviceToDevice);
    cudaMemcpyAsync(p_Wbhm + 512 * CC,  Whi, WSZ, cudaMemcpyDeviceToDevice);
    cudaMemcpyAsync(p_Wbhm + 1024 * CC, Wmi, WSZ, cudaMemcpyDeviceToDevice);
    cudaMemcpyAsync(p_bbhm,        bb,  512 * sizeof(float), cudaMemcpyDeviceToDevice);
    cudaMemcpyAsync(p_bbhm + 512,  bhi, 512 * sizeof(float), cudaMemcpyDeviceToDevice);
    cudaMemcpyAsync(p_bbhm + 1024, bmi, 512 * sizeof(float), cudaMemcpyDeviceToDevice);

    mean_kernel<<<(BB * CC + 255) / 256, 256>>>(img);
    // [vg|h0|m0] = relu(mean @ Wbhm^T + bbhm)
    tf32_gemm<1><<<tgrid(BB, 1536), 128>>>(p_mean, CC, p_mean, CC, KSINF,
                                           p_Wbhm, CC, p_bbhm, p_vghm, 1536, 1536, CC);
    hm_init_kernel<<<(BB * DD + 255) / 256, 256>>>();
    // Vf = relu(img @ Wa^T + ba)
    tf32_gemm<1><<<tgrid(BB * NN, DD), 128>>>(img, CC, img, CC, KSINF,
                                              Wa, CC, ba, p_Vf, DD, DD, CC);
    // zbase = Vf @ Wv^T
    tf32_gemm<0><<<tgrid(BB * NN, NN), 128>>>(p_Vf, DD, p_Vf, DD, KSINF,
                                              Wv, DD, nullptr, p_zbase, NN, NN, DD);
    xall_init_kernel<<<(TT * BB * XD1 + 255) / 256, 256>>>(emb, target);
    build_wcat_kernel<<<(GDIM * XDIM + 255) / 256, 256>>>(Wih, Whh, Wx, Wh2, bih, bhh);

    // ---- timestep loop ----
    for (int t = 0; t < TT; t++) {
        int cur = t & 1, nxt = cur ^ 1;
        // preact = [x_t | h_cur] @ Wcat^T + bcat
        tf32_gemm<0><<<tgrid(BB, GDIM), 128>>>(p_xall + (size_t)t * BB * XD1, XD1,
                                               p_h + (size_t)cur * BB * DD, DD, XD1,
                                               p_Wcat, XDIM, p_bcat, p_preact, GDIM, GDIM, XDIM);
        lstm_elem_kernel<<<(BB * DD + 255) / 256, 256>>>(cur, nxt);
        // H = relu(h2 @ WH^T); s = relu(u @ Wc^T + bc)  -- one launch, z selects
        hs_tf32<<<dim3(8, 2, 2), 128>>>(p_h + (size_t)nxt * BB * DD, p_u, WH, Wc, bc);
        attn_fused_kernel<<<BB, 256>>>(Wg, Wsm, wh, out_attn, t);
        // out = tanh(t1 @ Wfc^T + bfc)
        tf32_gemm<2><<<tgrid(BB, DD), 128>>>(p_t1, DD, p_t1, DD, KSINF,
                                             Wfc, DD, bfc, p_o512, DD, DD, DD);
        // logits into d_out at [:, t, :]
        tf32_gemm<0><<<tgrid(BB, VV), 128>>>(p_o512, DD, p_o512, DD, KSINF,
                                             Wp, DD, bp, out_logits + (size_t)t * VV,
                                             (long long)TT * VV, VV, DD);
    }

    log_softmax_kernel<<<BB * TT, 256>>>(out_logits);
}

// round 4
// speedup vs baseline: 1.9657x; 1.9657x over previous
#include <cuda_runtime.h>
#include <math.h>
#include <stdint.h>

// Problem constants
#define BB 128
#define NN 49
#define CC 2048
#define DD 512
#define EE 512
#define VV 10000
#define TT 20
#define XD1 1024       // x = [vg | we]
#define XDIM 1536      // x plus h
#define GDIM 2560      // 4D gates + D gate-linear
#define KSINF (1 << 30)

// ---------------- device scratch ----------------
__device__ __align__(16) float g_mean[BB * CC];
__device__ __align__(16) float g_vghm[BB * 1536];
__device__ __align__(16) float g_Vf[BB * NN * DD];
__device__ __align__(16) float g_zbase[BB * NN * NN];
__device__ __align__(16) float g_xall[TT * BB * XD1];
__device__ __align__(16) float g_Wcat[GDIM * XDIM];
__device__ __align__(16) float g_bcat[GDIM];
__device__ __align__(16) float g_Wbhm[1536 * CC];
__device__ __align__(16) float g_bbhm[1536];
__device__ __align__(16) float g_preact[BB * GDIM];
__device__ __align__(16) float g_h[2][BB * DD];
__device__ __align__(16) float g_m[2][BB * DD];
__device__ __align__(16) float g_u[BB * DD];
__device__ __align__(16) float g_Hb[BB * DD];
__device__ __align__(16) float g_sb[BB * DD];
__device__ __align__(16) float g_t1[BB * DD];
__device__ __align__(16) float g_o512[BB * DD];

__device__ __forceinline__ float sigf(float x) { return 1.0f / (1.0f + expf(-x)); }

__device__ __forceinline__ void mma8(float* c, const uint4 a, const uint2 b) {
    asm volatile("mma.sync.aligned.m16n8k8.row.col.f32.tf32.tf32.f32 "
        "{%0,%1,%2,%3}, {%4,%5,%6,%7}, {%8,%9}, {%0,%1,%2,%3};"
        : "+f"(c[0]), "+f"(c[1]), "+f"(c[2]), "+f"(c[3])
        : "r"(a.x), "r"(a.y), "r"(a.z), "r"(a.w), "r"(b.x), "r"(b.y));
}

__device__ __forceinline__ float4 ldg4(const float* p) {
    return *reinterpret_cast<const float4*>(p);
}

// ============ tf32 tensor-core GEMM body (v2) ============
// C[m,n] = act( sum_k A[m,k] * W[n,k] + bias[n] )
// 64x64x32 tiles, 128 threads (4 warps in 2x2, warp tile 32x32).
// smem: row-major [64][32] fp32 with chunk-XOR swizzle (c ^ (row&7)),
// vectorized STS.128 writes, conflict-free scalar LDS fragment reads,
// register prefetch double-buffering. Raw fp32 bits fed to tf32 MMA
// (hardware mantissa truncation).
// A rows assumed valid (M multiple of 64); W rows masked vs N.
// A split at ksplit: cols >= ksplit come from A2 ([x|h] concat).
template <int ACT>   // 0 none, 1 relu, 2 tanh
__device__ __forceinline__ void gemm_tc_body(
    const float* __restrict__ A, int lda,
    const float* __restrict__ A2, int lda2, int ksplit,
    const float* __restrict__ W, int ldw,
    const float* __restrict__ bias,
    float* __restrict__ C, long long ldc, int N, int K)
{
    __shared__ __align__(16) float sA[64 * 32];
    __shared__ __align__(16) float sB[64 * 32];

    const int tid = threadIdx.x;
    const int lane = tid & 31, w = tid >> 5;
    const int wm = (w >> 1) * 32, wn = (w & 1) * 32;
    const int m0 = blockIdx.y * 64, n0 = blockIdx.x * 64;
    const int lrow = tid >> 3;      // 0..15 (+16e)
    const int lc = tid & 7;         // k-chunk 0..7
    const int g = lane >> 2, q = lane & 3;
    const float4 z4 = make_float4(0.f, 0.f, 0.f, 0.f);

    float4 pa[4], pb[4];

    float acc[2][4][4];
#pragma unroll
    for (int i = 0; i < 2; i++)
#pragma unroll
        for (int j = 0; j < 4; j++)
#pragma unroll
            for (int u = 0; u < 4; u++) acc[i][j][u] = 0.f;

    const uint32_t* sAu = reinterpret_cast<const uint32_t*>(sA);
    const uint32_t* sBu = reinterpret_cast<const uint32_t*>(sB);

    // ---- prologue: load tile 0 ----
#pragma unroll
    for (int e = 0; e < 4; e++) {
        const int row = m0 + lrow + 16 * e;
        const int gk = lc * 4;
        pa[e] = (gk < ksplit) ? ldg4(A + (size_t)row * lda + gk)
                              : ldg4(A2 + (size_t)row * lda2 + (gk - ksplit));
        const int nrow = n0 + lrow + 16 * e;
        pb[e] = (nrow < N) ? ldg4(W + (size_t)nrow * ldw + gk) : z4;
    }
#pragma unroll
    for (int e = 0; e < 4; e++) {
        const int row = lrow + 16 * e;
        const int cs = lc ^ (row & 7);
        *reinterpret_cast<float4*>(&sA[row * 32 + cs * 4]) = pa[e];
        *reinterpret_cast<float4*>(&sB[row * 32 + cs * 4]) = pb[e];
    }

    for (int k0 = 0; k0 < K; k0 += 32) {
        __syncthreads();
        const bool more = (k0 + 32) < K;
        if (more) {
#pragma unroll
            for (int e = 0; e < 4; e++) {
                const int row = m0 + lrow + 16 * e;
                const int gk = k0 + 32 + lc * 4;
                pa[e] = (gk < ksplit) ? ldg4(A + (size_t)row * lda + gk)
                                      : ldg4(A2 + (size_t)row * lda2 + (gk - ksplit));
                const int nrow = n0 + lrow + 16 * e;
                pb[e] = (nrow < N) ? ldg4(W + (size_t)nrow * ldw + gk) : z4;
            }
        }
        // ---- compute current tile ----
#pragma unroll
        for (int kt = 0; kt < 4; kt++) {
            const int c0 = ((kt * 2) ^ g) * 4 + q;
            const int c1 = ((kt * 2 + 1) ^ g) * 4 + q;
            uint4 af[2];
#pragma unroll
            for (int i = 0; i < 2; i++) {
                const int r = wm + i * 16 + g;
                af[i].x = sAu[r * 32 + c0];
                af[i].y = sAu[(r + 8) * 32 + c0];
                af[i].z = sAu[r * 32 + c1];
                af[i].w = sAu[(r + 8) * 32 + c1];
            }
#pragma unroll
            for (int j = 0; j < 4; j++) {
                const int n = wn + j * 8 + g;
                uint2 bf;
                bf.x = sBu[n * 32 + c0];
                bf.y = sBu[n * 32 + c1];
                mma8(acc[0][j], af[0], bf);
                mma8(acc[1][j], af[1], bf);
            }
        }
        if (more) {
            __syncthreads();
#pragma unroll
            for (int e = 0; e < 4; e++) {
                const int row = lrow + 16 * e;
                const int cs = lc ^ (row & 7);
                *reinterpret_cast<float4*>(&sA[row * 32 + cs * 4]) = pa[e];
                *reinterpret_cast<float4*>(&sB[row * 32 + cs * 4]) = pb[e];
            }
        }
    }

    // ---- epilogue ----
#pragma unroll
    for (int i = 0; i < 2; i++) {
        const int r0 = m0 + wm + i * 16 + g;
#pragma unroll
        for (int j = 0; j < 4; j++) {
            const int col = n0 + wn + j * 8 + q * 2;
            float b0v = 0.f, b1v = 0.f;
            if (bias) {
                if (col < N)     b0v = bias[col];
                if (col + 1 < N) b1v = bias[col + 1];
            }
            float v00 = acc[i][j][0] + b0v, v01 = acc[i][j][1] + b1v;
            float v10 = acc[i][j][2] + b0v, v11 = acc[i][j][3] + b1v;
            if (ACT == 1) {
                v00 = fmaxf(v00, 0.f); v01 = fmaxf(v01, 0.f);
                v10 = fmaxf(v10, 0.f); v11 = fmaxf(v11, 0.f);
            } else if (ACT == 2) {
                v00 = tanhf(v00); v01 = tanhf(v01);
                v10 = tanhf(v10); v11 = tanhf(v11);
            }
            if (col < N) {
                C[(size_t)r0 * ldc + col] = v00;
                C[(size_t)(r0 + 8) * ldc + col] = v10;
            }
            if (col + 1 < N) {
                C[(size_t)r0 * ldc + col + 1] = v01;
                C[(size_t)(r0 + 8) * ldc + col + 1] = v11;
            }
        }
    }
}

template <int ACT>
__global__ void tf32_gemm(const float* __restrict__ A, int lda,
                          const float* __restrict__ A2, int lda2, int ksplit,
                          const float* __restrict__ W, int ldw,
                          const float* __restrict__ bias,
                          float* __restrict__ C, long long ldc, int N, int K)
{
    gemm_tc_body<ACT>(A, lda, A2, lda2, ksplit, W, ldw, bias, C, ldc, N, K);
}

// combined H and s GEMMs: blockIdx.z selects, single inlined body
__global__ void hs_tf32(const float* __restrict__ h2, const float* __restrict__ u,
                        const float* __restrict__ WH, const float* __restrict__ Wc,
                        const float* __restrict__ bc)
{
    const int sel = blockIdx.z;
    const float* Ain = sel ? u : h2;
    const float* Win = sel ? Wc : WH;
    const float* bin = sel ? bc : nullptr;
    float* Cout = sel ? g_sb : g_Hb;
    gemm_tc_body<1>(Ain, DD, Ain, DD, KSINF, Win, DD, bin, Cout, DD, DD, DD);
}

// ---------------- small kernels ----------------
__global__ void mean_kernel(const float* __restrict__ img)
{
    int idx = blockIdx.x * blockDim.x + threadIdx.x;
    if (idx >= BB * CC) return;
    int b = idx / CC, c = idx % CC;
    const float* p = img + (size_t)b * NN * CC + c;
    float s = 0.f;
#pragma unroll 7
    for (int n = 0; n < NN; n++) s += p[(size_t)n * CC];
    g_mean[idx] = s * (1.0f / NN);
}

__global__ void hm_init_kernel()
{
    int idx = blockIdx.x * blockDim.x + threadIdx.x;
    if (idx >= BB * DD) return;
    int b = idx >> 9, d = idx & 511;
    g_h[0][idx] = g_vghm[b * 1536 + 512 + d];
    g_m[0][idx] = g_vghm[b * 1536 + 1024 + d];
}

__global__ void xall_init_kernel(const float* __restrict__ emb, const int* __restrict__ target)
{
    int idx = blockIdx.x * blockDim.x + threadIdx.x;
    if (idx >= TT * BB * XD1) return;
    int j = idx % XD1;
    int tb = idx / XD1;
    int b = tb % BB;
    int t = tb / BB;
    float v;
    if (j < 512) v = g_vghm[b * 1536 + j];          // vg
    else if (t == 0) v = 0.f;
    else {
        int tok = target[b * TT + t - 1];
        v = emb[(size_t)tok * EE + (j - 512)];
    }
    g_xall[((size_t)t * BB + b) * XD1 + j] = v;
}

__global__ void build_wcat_kernel(const float* __restrict__ Wih, const float* __restrict__ Whh,
                                  const float* __restrict__ Wx, const float* __restrict__ Wh2,
                                  const float* __restrict__ bih, const float* __restrict__ bhh)
{
    int idx = blockIdx.x * blockDim.x + threadIdx.x;
    if (idx >= GDIM * XDIM) return;
    int r = idx / XDIM, c = idx % XDIM;
    float v;
    if (r < 2048) v = (c < 1024) ? Wih[(size_t)r * 1024 + c] : Whh[(size_t)r * 512 + (c - 1024)];
    else {
        int r2 = r - 2048;
        v = (c < 1024) ? Wx[(size_t)r2 * 1024 + c] : Wh2[(size_t)r2 * 512 + (c - 1024)];
    }
    g_Wcat[idx] = v;
    if (c == 0) g_bcat[r] = (r < 2048) ? (bih[r] + bhh[r]) : 0.f;
}

// LSTM nonlinearity (preact already includes bias from GEMM)
__global__ void lstm_elem_kernel(int cur, int nxt)
{
    int idx = blockIdx.x * blockDim.x + threadIdx.x;
    if (idx >= BB * DD) return;
    int b = idx >> 9, d = idx & 511;
    const float* p = g_preact + (size_t)b * GDIM;
    float gi = p[d], gf = p[512 + d], gg = p[1024 + d], go = p[1536 + d], gl = p[2048 + d];
    float m2 = sigf(gf) * g_m[cur][idx] + sigf(gi) * tanhf(gg);
    float tm2 = tanhf(m2);
    g_m[nxt][idx] = m2;
    g_h[nxt][idx] = sigf(go) * tm2;
    g_u[idx] = sigf(gl) * tm2;
}

// fused attention: gH, sWs, z, z2, softmax(50), attn out, ctx, t1=H+ctx
__global__ void attn_fused_kernel(const float* __restrict__ Wg, const float* __restrict__ Wsm,
                                  const float* __restrict__ wh,
                                  float* __restrict__ attn_out, int t)
{
    int b = blockIdx.x;
    __shared__ float sH[512], sS[512];
    __shared__ float gHs[49], sWss[49], zsh[50], wsh[49];
    int tid = threadIdx.x;  // 256
    for (int j = tid; j < 512; j += 256) {
        sH[j] = g_Hb[b * 512 + j];
        sS[j] = g_sb[b * 512 + j];
    }
    if (tid < 49) wsh[tid] = wh[tid];
    __syncthreads();

    int w = tid >> 5, lane = tid & 31;
    for (int n = w; n < 49; n += 8) {
        float a = 0.f, c = 0.f;
        const float* wg = Wg + (size_t)n * 512;
        const float* ws = Wsm + (size_t)n * 512;
        for (int d = lane; d < 512; d += 32) {
            a = fmaf(sH[d], wg[d], a);
            c = fmaf(sS[d], ws[d], c);
        }
#pragma unroll
        for (int off = 16; off; off >>= 1) {
            a += __shfl_down_sync(0xffffffffu, a, off);
            c += __shfl_down_sync(0xffffffffu, c, off);
        }
        if (lane == 0) { gHs[n] = a; sWss[n] = c; }
    }
    __syncthreads();

    if (tid < 49) {
        const float* zb = g_zbase + ((size_t)b * 49 + tid) * 49;
        float acc = 0.f;
#pragma unroll 7
        for (int k = 0; k < 49; k++) acc += tanhf(zb[k] + gHs[k]) * wsh[k];
        zsh[tid] = acc;
    } else if (tid == 49) {
        float acc = 0.f;
#pragma unroll 7
        for (int k = 0; k < 49; k++) acc += tanhf(sWss[k] + gHs[k]) * wsh[k];
        zsh[49] = acc;
    }
    __syncthreads();

    if (tid == 0) {
        float mx = -1e30f;
        for (int i = 0; i < 50; i++) mx = fmaxf(mx, zsh[i]);
        float sum = 0.f;
        for (int i = 0; i < 50; i++) { zsh[i] = expf(zsh[i] - mx); sum += zsh[i]; }
        float inv = 1.f / sum;
        for (int i = 0; i < 50; i++) zsh[i] *= inv;
    }
    __syncthreads();

    if (tid < 49) attn_out[((size_t)b * TT + t) * 49 + tid] = zsh[tid];

    float a50 = zsh[49];
    for (int d = tid; d < 512; d += 256) {
        float acc = a50 * sS[d];
#pragma unroll 7
        for (int n = 0; n < 49; n++)
            acc = fmaf(zsh[n], g_Vf[((size_t)b * 49 + n) * 512 + d], acc);
        g_t1[b * 512 + d] = sH[d] + acc;
    }
}

__global__ void log_softmax_kernel(float* __restrict__ logits)
{
    int row = blockIdx.x;  // B*T rows
    float* x = logits + (size_t)row * VV;
    __shared__ float red[256];
    int tid = threadIdx.x;
    float mx = -1e30f;
    for (int i = tid; i < VV; i += 256) mx = fmaxf(mx, x[i]);
    red[tid] = mx; __syncthreads();
    for (int s = 128; s; s >>= 1) { if (tid < s) red[tid] = fmaxf(red[tid], red[tid + s]); __syncthreads(); }
    mx = red[0];
    __syncthreads();
    float sum = 0.f;
    for (int i = tid; i < VV; i += 256) sum += expf(x[i] - mx);
    red[tid] = sum; __syncthreads();
    for (int s = 128; s; s >>= 1) { if (tid < s) red[tid] += red[tid + s]; __syncthreads(); }
    float lse = mx + logf(red[0]);
    for (int i = tid; i < VV; i += 256) x[i] -= lse;
}

// ---------------- host ----------------
static inline dim3 tgrid(int M, int N) { return dim3((N + 63) / 64, (M + 63) / 64); }

extern "C" void kernel_launch(void* const* d_in, const int* in_sizes, int n_in,
                              void* d_out, int out_size)
{
    const float* img    = (const float*)d_in[0];
    const int*   target = (const int*)d_in[1];
    const float* emb    = (const float*)d_in[2];
    const float* Wa  = (const float*)d_in[3];  const float* ba  = (const float*)d_in[4];
    const float* Wb  = (const float*)d_in[5];  const float* bb  = (const float*)d_in[6];
    const float* Whi = (const float*)d_in[7];  const float* bhi = (const float*)d_in[8];
    const float* Wmi = (const float*)d_in[9];  const float* bmi = (const float*)d_in[10];
    const float* Wih = (const float*)d_in[11]; const float* bih = (const float*)d_in[12];
    const float* Whh = (const float*)d_in[13]; const float* bhh = (const float*)d_in[14];
    const float* Wv  = (const float*)d_in[15];
    const float* Wg  = (const float*)d_in[16];
    const float* wh  = (const float*)d_in[17];
    const float* WH  = (const float*)d_in[18];
    const float* Wx  = (const float*)d_in[19];
    const float* Wh2 = (const float*)d_in[20];
    const float* Wsm = (const float*)d_in[21];
    const float* Wc  = (const float*)d_in[22]; const float* bc  = (const float*)d_in[23];
    const float* Wfc = (const float*)d_in[24]; const float* bfc = (const float*)d_in[25];
    const float* Wp  = (const float*)d_in[26]; const float* bp  = (const float*)d_in[27];

    float* out_logits = (float*)d_out;                               // [B,T,VOC]
    float* out_attn   = (float*)d_out + (size_t)BB * TT * VV;        // [B,T,N]

    float *p_mean, *p_vghm, *p_Vf, *p_xall, *p_Wbhm, *p_bbhm, *p_Wcat, *p_bcat;
    float *p_preact, *p_h, *p_u, *p_t1, *p_o512, *p_zbase;
    cudaGetSymbolAddress((void**)&p_mean,  g_mean);
    cudaGetSymbolAddress((void**)&p_vghm,  g_vghm);
    cudaGetSymbolAddress((void**)&p_Vf,    g_Vf);
    cudaGetSymbolAddress((void**)&p_zbase, g_zbase);
    cudaGetSymbolAddress((void**)&p_xall,  g_xall);
    cudaGetSymbolAddress((void**)&p_Wbhm,  g_Wbhm);
    cudaGetSymbolAddress((void**)&p_bbhm,  g_bbhm);
    cudaGetSymbolAddress((void**)&p_Wcat,  g_Wcat);
    cudaGetSymbolAddress((void**)&p_bcat,  g_bcat);
    cudaGetSymbolAddress((void**)&p_preact,g_preact);
    cudaGetSymbolAddress((void**)&p_h,     g_h);
    cudaGetSymbolAddress((void**)&p_u,     g_u);
    cudaGetSymbolAddress((void**)&p_t1,    g_t1);
    cudaGetSymbolAddress((void**)&p_o512,  g_o512);

    // ---- precompute ----
    const size_t WSZ = (size_t)DD * CC * sizeof(float);
    cudaMemcpyAsync(p_Wbhm,             Wb,  WSZ, cudaMemcpyDeviceToDevice);
    cudaMemcpyAsync(p_Wbhm + 512 * CC,  Whi, WSZ, cudaMemcpyDeviceToDevice);
    cudaMemcpyAsync(p_Wbhm + 1024 * CC, Wmi, WSZ, cudaMemcpyDeviceToDevice);
    cudaMemcpyAsync(p_bbhm,        bb,  512 * sizeof(float), cudaMemcpyDeviceToDevice);
    cudaMemcpyAsync(p_bbhm + 512,  bhi, 512 * sizeof(float), cudaMemcpyDeviceToDevice);
    cudaMemcpyAsync(p_bbhm + 1024, bmi, 512 * sizeof(float), cudaMemcpyDeviceToDevice);

    mean_kernel<<<(BB * CC + 255) / 256, 256>>>(img);
    // [vg|h0|m0] = relu(mean @ Wbhm^T + bbhm)
    tf32_gemm<1><<<tgrid(BB, 1536), 128>>>(p_mean, CC, p_mean, CC, KSINF,
                                           p_Wbhm, CC, p_bbhm, p_vghm, 1536, 1536, CC);
    hm_init_kernel<<<(BB * DD + 255) / 256, 256>>>();
    // Vf = relu(img @ Wa^T + ba)
    tf32_gemm<1><<<tgrid(BB * NN, DD), 128>>>(img, CC, img, CC, KSINF,
                                              Wa, CC, ba, p_Vf, DD, DD, CC);
    // zbase = Vf @ Wv^T
    tf32_gemm<0><<<tgrid(BB * NN, NN), 128>>>(p_Vf, DD, p_Vf, DD, KSINF,
                                              Wv, DD, nullptr, p_zbase, NN, NN, DD);
    xall_init_kernel<<<(TT * BB * XD1 + 255) / 256, 256>>>(emb, target);
    build_wcat_kernel<<<(GDIM * XDIM + 255) / 256, 256>>>(Wih, Whh, Wx, Wh2, bih, bhh);

    // ---- timestep loop ----
    for (int t = 0; t < TT; t++) {
        int cur = t & 1, nxt = cur ^ 1;
        // preact = [x_t | h_cur] @ Wcat^T + bcat
        tf32_gemm<0><<<tgrid(BB, GDIM), 128>>>(p_xall + (size_t)t * BB * XD1, XD1,
                                               p_h + (size_t)cur * BB * DD, DD, XD1,
                                               p_Wcat, XDIM, p_bcat, p_preact, GDIM, GDIM, XDIM);
        lstm_elem_kernel<<<(BB * DD + 255) / 256, 256>>>(cur, nxt);
        // H = relu(h2 @ WH^T); s = relu(u @ Wc^T + bc)  -- one launch, z selects
        hs_tf32<<<dim3(8, 2, 2), 128>>>(p_h + (size_t)nxt * BB * DD, p_u, WH, Wc, bc);
        attn_fused_kernel<<<BB, 256>>>(Wg, Wsm, wh, out_attn, t);
        // out = tanh(t1 @ Wfc^T + bfc)
        tf32_gemm<2><<<tgrid(BB, DD), 128>>>(p_t1, DD, p_t1, DD, KSINF,
                                             Wfc, DD, bfc, p_o512, DD, DD, DD);
        // logits into d_out at [:, t, :]
        tf32_gemm<0><<<tgrid(BB, VV), 128>>>(p_o512, DD, p_o512, DD, KSINF,
                                             Wp, DD, bp, out_logits + (size_t)t * VV,
                                             (long long)TT * VV, VV, DD);
    }

    log_softmax_kernel<<<BB * TT, 256>>>(out_logits);
}

// round 5
// speedup vs baseline: 2.2169x; 1.1278x over previous
#include <cuda_runtime.h>
#include <cuda_bf16.h>
#include <math.h>
#include <stdint.h>

// Problem constants
#define BB 128
#define NN 49
#define CC 2048
#define DD 512
#define EE 512
#define VV 10000
#define TT 20
#define XD1 1024       // x = [vg | we]
#define XDIM 1536      // x plus h
#define GDIM 2560      // 4D gates + D gate-linear
#define KSINF (1 << 30)

typedef __nv_bfloat16 bf16;

// ---------------- device scratch ----------------
// bf16 operand buffers
__device__ __align__(16) bf16 g_imgb[BB * NN * CC];
__device__ __align__(16) bf16 g_meanb[BB * CC];
__device__ __align__(16) bf16 g_Wbhmb[1536 * CC];
__device__ __align__(16) bf16 g_Wab[DD * CC];
__device__ __align__(16) bf16 g_Wvb[NN * DD];
__device__ __align__(16) bf16 g_Vfb[BB * NN * DD];
__device__ __align__(16) bf16 g_xallb[TT * BB * XD1];
__device__ __align__(16) bf16 g_Wcatb[GDIM * XDIM];
__device__ __align__(16) bf16 g_WHb[DD * DD];
__device__ __align__(16) bf16 g_Wcb[DD * DD];
__device__ __align__(16) bf16 g_Wfcb[DD * DD];
__device__ __align__(16) bf16 g_Wpb[VV * DD];
__device__ __align__(16) bf16 g_hb[2][BB * DD];
__device__ __align__(16) bf16 g_ub[BB * DD];
__device__ __align__(16) bf16 g_t1b[BB * DD];
__device__ __align__(16) bf16 g_o512b[BB * DD];
// fp32 buffers
__device__ __align__(16) float g_vghm[BB * 1536];
__device__ __align__(16) float g_Vf[BB * NN * DD];
__device__ __align__(16) float g_zbase[BB * NN * NN];
__device__ __align__(16) float g_bbhm[1536];
__device__ __align__(16) float g_bcat[GDIM];
__device__ __align__(16) float g_preact[BB * GDIM];
__device__ __align__(16) float g_m[2][BB * DD];
__device__ __align__(16) float g_Hb[BB * DD];
__device__ __align__(16) float g_sb[BB * DD];

__device__ __forceinline__ float sigf(float x) { return 1.0f / (1.0f + expf(-x)); }

__device__ __forceinline__ uint4 ldsm4(uint32_t addr) {
    uint4 r;
    asm volatile("ldmatrix.sync.aligned.m8n8.x4.shared.b16 {%0,%1,%2,%3}, [%4];"
                 : "=r"(r.x), "=r"(r.y), "=r"(r.z), "=r"(r.w) : "r"(addr));
    return r;
}

__device__ __forceinline__ void mma16(float* c, const uint4 a, uint32_t b0, uint32_t b1) {
    asm volatile("mma.sync.aligned.m16n8k16.row.col.f32.bf16.bf16.f32 "
        "{%0,%1,%2,%3}, {%4,%5,%6,%7}, {%8,%9}, {%0,%1,%2,%3};"
        : "+f"(c[0]), "+f"(c[1]), "+f"(c[2]), "+f"(c[3])
        : "r"(a.x), "r"(a.y), "r"(a.z), "r"(a.w), "r"(b0), "r"(b1));
}

// ============ bf16 tensor-core GEMM body ============
// C[m,n] = act( sum_k A[m,k] * W[n,k] + bias[n] ), fp32 accumulate.
// 64x64x32 tiles, 128 threads (4 warps in 2x2, warp tile 32x32).
// smem rows padded to 40 bf16 (80B): (5*row + chunk) mod 8 spreads the
// 16B chunks over the bank cycle -> conflict-free ldmatrix & STS.128.
// A rows assumed valid (M multiple of 64); W rows masked vs N.
// A split at ksplit (elements, mult of 8): cols >= ksplit come from A2.
// OUT: 0 = fp32 C only, 1 = fp32 C + bf16 Cb, 2 = bf16 Cb only.
template <int ACT, int OUT>   // ACT: 0 none, 1 relu, 2 tanh
__device__ __forceinline__ void gemm_bf_body(
    const bf16* __restrict__ A, int lda,
    const bf16* __restrict__ A2, int lda2, int ksplit,
    const bf16* __restrict__ W, int ldw,
    const float* __restrict__ bias,
    float* __restrict__ C, bf16* __restrict__ Cb,
    long long ldc, int N, int K)
{
    __shared__ __align__(16) bf16 sA[64 * 40];
    __shared__ __align__(16) bf16 sB[64 * 40];

    const int tid = threadIdx.x;
    const int lane = tid & 31, w = tid >> 5;
    const int wm = (w >> 1) * 32, wn = (w & 1) * 32;
    const int m0 = blockIdx.y * 64, n0 = blockIdx.x * 64;
    const int g = lane >> 2, q = lane & 3;
    // global->smem: each thread owns one row (tid>>1) and 2 chunks of 8 bf16
    const int grow = tid >> 1;
    const int gc0 = (tid & 1) * 2;
    const uint4 z4 = make_uint4(0, 0, 0, 0);

    const uint32_t baseA = (uint32_t)__cvta_generic_to_shared(sA);
    const uint32_t baseB = (uint32_t)__cvta_generic_to_shared(sB);
    // ldmatrix lane addresses
    const int rA = wm + (lane & 7) + ((lane >> 3) & 1) * 8;
    const uint32_t offA0 = baseA + (uint32_t)(rA * 40 + (lane >> 4) * 8) * 2;
    const int rB = wn + (lane & 7);
    const uint32_t offB0 = baseB + (uint32_t)(rB * 40 + (lane >> 3) * 8) * 2;

    float acc[2][4][4];
#pragma unroll
    for (int i = 0; i < 2; i++)
#pragma unroll
        for (int j = 0; j < 4; j++)
#pragma unroll
            for (int u = 0; u < 4; u++) acc[i][j][u] = 0.f;

    uint4 pa[2], pb[2];

    auto load_regs = [&](int k0) {
#pragma unroll
        for (int e = 0; e < 2; e++) {
            const int gk = k0 + (gc0 + e) * 8;
            pa[e] = (gk < ksplit)
                ? *reinterpret_cast<const uint4*>(A + (size_t)(m0 + grow) * lda + gk)
                : *reinterpret_cast<const uint4*>(A2 + (size_t)(m0 + grow) * lda2 + (gk - ksplit));
            pb[e] = (n0 + grow < N)
                ? *reinterpret_cast<const uint4*>(W + (size_t)(n0 + grow) * ldw + gk)
                : z4;
        }
    };
    auto store_smem = [&]() {
#pragma unroll
        for (int e = 0; e < 2; e++) {
            *reinterpret_cast<uint4*>(&sA[grow * 40 + (gc0 + e) * 8]) = pa[e];
            *reinterpret_cast<uint4*>(&sB[grow * 40 + (gc0 + e) * 8]) = pb[e];
        }
    };

    load_regs(0);
    store_smem();

    for (int k0 = 0; k0 < K; k0 += 32) {
        __syncthreads();
        const bool more = (k0 + 32) < K;
        if (more) load_regs(k0 + 32);

        uint4 bfr[4];
#pragma unroll
        for (int j = 0; j < 4; j++) bfr[j] = ldsm4(offB0 + j * 640);
#pragma unroll
        for (int kt = 0; kt < 2; kt++) {
            uint4 af0 = ldsm4(offA0 + kt * 32);
            uint4 af1 = ldsm4(offA0 + 1280 + kt * 32);
#pragma unroll
            for (int j = 0; j < 4; j++) {
                const uint32_t b0 = kt ? bfr[j].z : bfr[j].x;
                const uint32_t b1 = kt ? bfr[j].w : bfr[j].y;
                mma16(acc[0][j], af0, b0, b1);
                mma16(acc[1][j], af1, b0, b1);
            }
        }
        if (more) {
            __syncthreads();
            store_smem();
        }
    }

    // ---- epilogue ----
#pragma unroll
    for (int i = 0; i < 2; i++) {
        const int r0 = m0 + wm + i * 16 + g;
#pragma unroll
        for (int j = 0; j < 4; j++) {
            const int col = n0 + wn + j * 8 + q * 2;
            float b0v = 0.f, b1v = 0.f;
            if (bias) {
                if (col < N)     b0v = bias[col];
                if (col + 1 < N) b1v = bias[col + 1];
            }
            float v00 = acc[i][j][0] + b0v, v01 = acc[i][j][1] + b1v;
            float v10 = acc[i][j][2] + b0v, v11 = acc[i][j][3] + b1v;
            if (ACT == 1) {
                v00 = fmaxf(v00, 0.f); v01 = fmaxf(v01, 0.f);
                v10 = fmaxf(v10, 0.f); v11 = fmaxf(v11, 0.f);
            } else if (ACT == 2) {
                v00 = tanhf(v00); v01 = tanhf(v01);
                v10 = tanhf(v10); v11 = tanhf(v11);
            }
            if (col < N) {
                if (OUT != 2) {
                    C[(size_t)r0 * ldc + col] = v00;
                    C[(size_t)(r0 + 8) * ldc + col] = v10;
                }
                if (OUT != 0) {
                    Cb[(size_t)r0 * ldc + col] = __float2bfloat16(v00);
                    Cb[(size_t)(r0 + 8) * ldc + col] = __float2bfloat16(v10);
                }
            }
            if (col + 1 < N) {
                if (OUT != 2) {
                    C[(size_t)r0 * ldc + col + 1] = v01;
                    C[(size_t)(r0 + 8) * ldc + col + 1] = v11;
                }
                if (OUT != 0) {
                    Cb[(size_t)r0 * ldc + col + 1] = __float2bfloat16(v01);
                    Cb[(size_t)(r0 + 8) * ldc + col + 1] = __float2bfloat16(v11);
                }
            }
        }
    }
}

template <int ACT, int OUT>
__global__ __launch_bounds__(128) void gemm_bf(
    const bf16* __restrict__ A, int lda,
    const bf16* __restrict__ A2, int lda2, int ksplit,
    const bf16* __restrict__ W, int ldw,
    const float* __restrict__ bias,
    float* __restrict__ C, bf16* __restrict__ Cb, long long ldc, int N, int K)
{
    gemm_bf_body<ACT, OUT>(A, lda, A2, lda2, ksplit, W, ldw, bias, C, Cb, ldc, N, K);
}

// combined H and s GEMMs: blockIdx.z selects
__global__ __launch_bounds__(128) void hs_bf(const float* __restrict__ bc)
{
    const int sel = blockIdx.z;
    const bf16* Ain = sel ? g_ub : g_hb[1];      // caller ensures h index
    const bf16* Ain0 = sel ? g_ub : g_hb[0];
    (void)Ain0;
    const bf16* Win = sel ? g_Wcb : g_WHb;
    const float* bin = sel ? bc : nullptr;
    float* Cout = sel ? g_sb : g_Hb;
    gemm_bf_body<1, 0>(Ain, DD, Ain, DD, KSINF, Win, DD, bin, Cout, nullptr, DD, DD, DD);
}

// variant with explicit h buffer index
__global__ __launch_bounds__(128) void hs_bf_idx(int nxt, const float* __restrict__ bc)
{
    const int sel = blockIdx.z;
    const bf16* Ain = sel ? g_ub : g_hb[nxt];
    const bf16* Win = sel ? g_Wcb : g_WHb;
    const float* bin = sel ? bc : nullptr;
    float* Cout = sel ? g_sb : g_Hb;
    gemm_bf_body<1, 0>(Ain, DD, Ain, DD, KSINF, Win, DD, bin, Cout, nullptr, DD, DD, DD);
}

// ---------------- conversion / setup kernels ----------------
__global__ void cvt_bf16_kernel(const float* __restrict__ in, bf16* __restrict__ out, int n4)
{
    int idx = blockIdx.x * blockDim.x + threadIdx.x;
    if (idx >= n4) return;
    float4 v = reinterpret_cast<const float4*>(in)[idx];
    __nv_bfloat162 lo = __floats2bfloat162_rn(v.x, v.y);
    __nv_bfloat162 hi = __floats2bfloat162_rn(v.z, v.w);
    reinterpret_cast<__nv_bfloat162*>(out)[idx * 2]     = lo;
    reinterpret_cast<__nv_bfloat162*>(out)[idx * 2 + 1] = hi;
}

__global__ void mean_kernel(const float* __restrict__ img)
{
    int idx = blockIdx.x * blockDim.x + threadIdx.x;
    if (idx >= BB * CC) return;
    int b = idx / CC, c = idx % CC;
    const float* p = img + (size_t)b * NN * CC + c;
    float s = 0.f;
#pragma unroll 7
    for (int n = 0; n < NN; n++) s += p[(size_t)n * CC];
    g_meanb[idx] = __float2bfloat16(s * (1.0f / NN));
}

__global__ void build_wbhm_kernel(const float* __restrict__ Wb, const float* __restrict__ Whi,
                                  const float* __restrict__ Wmi,
                                  const float* __restrict__ bb, const float* __restrict__ bhi,
                                  const float* __restrict__ bmi)
{
    int idx = blockIdx.x * blockDim.x + threadIdx.x;
    if (idx >= 1536 * CC) return;
    int r = idx / CC, c = idx % CC;
    float v;
    if (r < 512)       v = Wb[(size_t)r * CC + c];
    else if (r < 1024) v = Whi[(size_t)(r - 512) * CC + c];
    else               v = Wmi[(size_t)(r - 1024) * CC + c];
    g_Wbhmb[idx] = __float2bfloat16(v);
    if (c == 0) g_bbhm[r] = (r < 512) ? bb[r] : (r < 1024 ? bhi[r - 512] : bmi[r - 1024]);
}

__global__ void build_wcat_kernel(const float* __restrict__ Wih, const float* __restrict__ Whh,
                                  const float* __restrict__ Wx, const float* __restrict__ Wh2,
                                  const float* __restrict__ bih, const float* __restrict__ bhh)
{
    int idx = blockIdx.x * blockDim.x + threadIdx.x;
    if (idx >= GDIM * XDIM) return;
    int r = idx / XDIM, c = idx % XDIM;
    float v;
    if (r < 2048) v = (c < 1024) ? Wih[(size_t)r * 1024 + c] : Whh[(size_t)r * 512 + (c - 1024)];
    else {
        int r2 = r - 2048;
        v = (c < 1024) ? Wx[(size_t)r2 * 1024 + c] : Wh2[(size_t)r2 * 512 + (c - 1024)];
    }
    g_Wcatb[idx] = __float2bfloat16(v);
    if (c == 0) g_bcat[r] = (r < 2048) ? (bih[r] + bhh[r]) : 0.f;
}

__global__ void hm_init_kernel()
{
    int idx = blockIdx.x * blockDim.x + threadIdx.x;
    if (idx >= BB * DD) return;
    int b = idx >> 9, d = idx & 511;
    g_hb[0][idx] = __float2bfloat16(g_vghm[b * 1536 + 512 + d]);
    g_m[0][idx] = g_vghm[b * 1536 + 1024 + d];
}

__global__ void xall_init_kernel(const float* __restrict__ emb, const int* __restrict__ target)
{
    int idx = blockIdx.x * blockDim.x + threadIdx.x;
    if (idx >= TT * BB * XD1) return;
    int j = idx % XD1;
    int tb = idx / XD1;
    int b = tb % BB;
    int t = tb / BB;
    float v;
    if (j < 512) v = g_vghm[b * 1536 + j];          // vg
    else if (t == 0) v = 0.f;
    else {
        int tok = target[b * TT + t - 1];
        v = emb[(size_t)tok * EE + (j - 512)];
    }
    g_xallb[((size_t)t * BB + b) * XD1 + j] = __float2bfloat16(v);
}

// LSTM nonlinearity (preact already includes bias from GEMM)
__global__ void lstm_elem_kernel(int cur, int nxt)
{
    int idx = blockIdx.x * blockDim.x + threadIdx.x;
    if (idx >= BB * DD) return;
    int b = idx >> 9, d = idx & 511;
    const float* p = g_preact + (size_t)b * GDIM;
    float gi = p[d], gf = p[512 + d], gg = p[1024 + d], go = p[1536 + d], gl = p[2048 + d];
    float m2 = sigf(gf) * g_m[cur][idx] + sigf(gi) * tanhf(gg);
    float tm2 = tanhf(m2);
    g_m[nxt][idx] = m2;
    g_hb[nxt][idx] = __float2bfloat16(sigf(go) * tm2);
    g_ub[idx] = __float2bfloat16(sigf(gl) * tm2);
}

// fused attention: gH, sWs, z, z2, softmax(50), attn out, ctx, t1=H+ctx
__global__ void attn_fused_kernel(const float* __restrict__ Wg, const float* __restrict__ Wsm,
                                  const float* __restrict__ wh,
                                  float* __restrict__ attn_out, int t)
{
    int b = blockIdx.x;
    __shared__ float sH[512], sS[512];
    __shared__ float gHs[49], sWss[49], zsh[50], wsh[49];
    int tid = threadIdx.x;  // 256
    for (int j = tid; j < 512; j += 256) {
        sH[j] = g_Hb[b * 512 + j];
        sS[j] = g_sb[b * 512 + j];
    }
    if (tid < 49) wsh[tid] = wh[tid];
    __syncthreads();

    int w = tid >> 5, lane = tid & 31;
    for (int n = w; n < 49; n += 8) {
        float a = 0.f, c = 0.f;
        const float* wg = Wg + (size_t)n * 512;
        const float* ws = Wsm + (size_t)n * 512;
        for (int d = lane; d < 512; d += 32) {
            a = fmaf(sH[d], wg[d], a);
            c = fmaf(sS[d], ws[d], c);
        }
#pragma unroll
        for (int off = 16; off; off >>= 1) {
            a += __shfl_down_sync(0xffffffffu, a, off);
            c += __shfl_down_sync(0xffffffffu, c, off);
        }
        if (lane == 0) { gHs[n] = a; sWss[n] = c; }
    }
    __syncthreads();

    if (tid < 49) {
        const float* zb = g_zbase + ((size_t)b * 49 + tid) * 49;
        float acc = 0.f;
#pragma unroll 7
        for (int k = 0; k < 49; k++) acc += tanhf(zb[k] + gHs[k]) * wsh[k];
        zsh[tid] = acc;
    } else if (tid == 49) {
        float acc = 0.f;
#pragma unroll 7
        for (int k = 0; k < 49; k++) acc += tanhf(sWss[k] + gHs[k]) * wsh[k];
        zsh[49] = acc;
    }
    __syncthreads();

    if (tid == 0) {
        float mx = -1e30f;
        for (int i = 0; i < 50; i++) mx = fmaxf(mx, zsh[i]);
        float sum = 0.f;
        for (int i = 0; i < 50; i++) { zsh[i] = expf(zsh[i] - mx); sum += zsh[i]; }
        float inv = 1.f / sum;
        for (int i = 0; i < 50; i++) zsh[i] *= inv;
    }
    __syncthreads();

    if (tid < 49) attn_out[((size_t)b * TT + t) * 49 + tid] = zsh[tid];

    float a50 = zsh[49];
    for (int d = tid; d < 512; d += 256) {
        float acc = a50 * sS[d];
#pragma unroll 7
        for (int n = 0; n < 49; n++)
            acc = fmaf(zsh[n], g_Vf[((size_t)b * 49 + n) * 512 + d], acc);
        g_t1b[b * 512 + d] = __float2bfloat16(sH[d] + acc);
    }
}

__global__ void log_softmax_kernel(float* __restrict__ logits)
{
    int row = blockIdx.x;  // B*T rows
    float* x = logits + (size_t)row * VV;
    __shared__ float red[256];
    int tid = threadIdx.x;
    float mx = -1e30f;
    for (int i = tid; i < VV; i += 256) mx = fmaxf(mx, x[i]);
    red[tid] = mx; __syncthreads();
    for (int s = 128; s; s >>= 1) { if (tid < s) red[tid] = fmaxf(red[tid], red[tid + s]); __syncthreads(); }
    mx = red[0];
    __syncthreads();
    float sum = 0.f;
    for (int i = tid; i < VV; i += 256) sum += expf(x[i] - mx);
    red[tid] = sum; __syncthreads();
    for (int s = 128; s; s >>= 1) { if (tid < s) red[tid] += red[tid + s]; __syncthreads(); }
    float lse = mx + logf(red[0]);
    for (int i = tid; i < VV; i += 256) x[i] -= lse;
}

// ---------------- host ----------------
static inline dim3 tgrid(int M, int N) { return dim3((N + 63) / 64, (M + 63) / 64); }

extern "C" void kernel_launch(void* const* d_in, const int* in_sizes, int n_in,
                              void* d_out, int out_size)
{
    const float* img    = (const float*)d_in[0];
    const int*   target = (const int*)d_in[1];
    const float* emb    = (const float*)d_in[2];
    const float* Wa  = (const float*)d_in[3];  const float* ba  = (const float*)d_in[4];
    const float* Wb  = (const float*)d_in[5];  const float* bb  = (const float*)d_in[6];
    const float* Whi = (const float*)d_in[7];  const float* bhi = (const float*)d_in[8];
    const float* Wmi = (const float*)d_in[9];  const float* bmi = (const float*)d_in[10];
    const float* Wih = (const float*)d_in[11]; const float* bih = (const float*)d_in[12];
    const float* Whh = (const float*)d_in[13]; const float* bhh = (const float*)d_in[14];
    const float* Wv  = (const float*)d_in[15];
    const float* Wg  = (const float*)d_in[16];
    const float* wh  = (const float*)d_in[17];
    const float* WH  = (const float*)d_in[18];
    const float* Wx  = (const float*)d_in[19];
    const float* Wh2 = (const float*)d_in[20];
    const float* Wsm = (const float*)d_in[21];
    const float* Wc  = (const float*)d_in[22]; const float* bc  = (const float*)d_in[23];
    const float* Wfc = (const float*)d_in[24]; const float* bfc = (const float*)d_in[25];
    const float* Wp  = (const float*)d_in[26]; const float* bp  = (const float*)d_in[27];

    float* out_logits = (float*)d_out;                               // [B,T,VOC]
    float* out_attn   = (float*)d_out + (size_t)BB * TT * VV;        // [B,T,N]

    bf16 *p_imgb, *p_meanb, *p_Wbhmb, *p_Wab, *p_Wvb, *p_Vfb, *p_xallb, *p_Wcatb;
    bf16 *p_WHb, *p_Wcb, *p_Wfcb, *p_Wpb, *p_hb, *p_ub, *p_t1b, *p_o512b;
    float *p_vghm, *p_Vf, *p_zbase, *p_bbhm, *p_bcat, *p_preact;
    cudaGetSymbolAddress((void**)&p_imgb,  g_imgb);
    cudaGetSymbolAddress((void**)&p_meanb, g_meanb);
    cudaGetSymbolAddress((void**)&p_Wbhmb, g_Wbhmb);
    cudaGetSymbolAddress((void**)&p_Wab,   g_Wab);
    cudaGetSymbolAddress((void**)&p_Wvb,   g_Wvb);
    cudaGetSymbolAddress((void**)&p_Vfb,   g_Vfb);
    cudaGetSymbolAddress((void**)&p_xallb, g_xallb);
    cudaGetSymbolAddress((void**)&p_Wcatb, g_Wcatb);
    cudaGetSymbolAddress((void**)&p_WHb,   g_WHb);
    cudaGetSymbolAddress((void**)&p_Wcb,   g_Wcb);
    cudaGetSymbolAddress((void**)&p_Wfcb,  g_Wfcb);
    cudaGetSymbolAddress((void**)&p_Wpb,   g_Wpb);
    cudaGetSymbolAddress((void**)&p_hb,    g_hb);
    cudaGetSymbolAddress((void**)&p_ub,    g_ub);
    cudaGetSymbolAddress((void**)&p_t1b,   g_t1b);
    cudaGetSymbolAddress((void**)&p_o512b, g_o512b);
    cudaGetSymbolAddress((void**)&p_vghm,  g_vghm);
    cudaGetSymbolAddress((void**)&p_Vf,    g_Vf);
    cudaGetSymbolAddress((void**)&p_zbase, g_zbase);
    cudaGetSymbolAddress((void**)&p_bbhm,  g_bbhm);
    cudaGetSymbolAddress((void**)&p_bcat,  g_bcat);
    cudaGetSymbolAddress((void**)&p_preact,g_preact);

    // ---- precompute: conversions ----
    auto cvt = [&](const float* in, bf16* out, int n) {
        cvt_bf16_kernel<<<(n / 4 + 255) / 256, 256>>>(in, out, n / 4);
    };
    cvt(img, p_imgb, BB * NN * CC);
    cvt(Wa,  p_Wab,  DD * CC);
    cvt(Wv,  p_Wvb,  NN * DD);
    cvt(WH,  p_WHb,  DD * DD);
    cvt(Wc,  p_Wcb,  DD * DD);
    cvt(Wfc, p_Wfcb, DD * DD);
    cvt(Wp,  p_Wpb,  VV * DD);
    build_wbhm_kernel<<<(1536 * CC + 255) / 256, 256>>>(Wb, Whi, Wmi, bb, bhi, bmi);
    build_wcat_kernel<<<(GDIM * XDIM + 255) / 256, 256>>>(Wih, Whh, Wx, Wh2, bih, bhh);
    mean_kernel<<<(BB * CC + 255) / 256, 256>>>(img);

    // [vg|h0|m0] = relu(mean @ Wbhm^T + bbhm)   (fp32 out)
    gemm_bf<1, 0><<<tgrid(BB, 1536), 128>>>(p_meanb, CC, p_meanb, CC, KSINF,
                                            p_Wbhmb, CC, p_bbhm, p_vghm, nullptr, 1536, 1536, CC);
    hm_init_kernel<<<(BB * DD + 255) / 256, 256>>>();
    // Vf = relu(imgb @ Wa^T + ba)  (fp32 + bf16 out)
    gemm_bf<1, 1><<<tgrid(BB * NN, DD), 128>>>(p_imgb, CC, p_imgb, CC, KSINF,
                                               p_Wab, CC, ba, p_Vf, p_Vfb, DD, DD, CC);
    // zbase = Vfb @ Wv^T  (fp32 out)
    gemm_bf<0, 0><<<tgrid(BB * NN, NN), 128>>>(p_Vfb, DD, p_Vfb, DD, KSINF,
                                               p_Wvb, DD, nullptr, p_zbase, nullptr, NN, NN, DD);
    xall_init_kernel<<<(TT * BB * XD1 + 255) / 256, 256>>>(emb, target);

    // ---- timestep loop ----
    for (int t = 0; t < TT; t++) {
        int cur = t & 1, nxt = cur ^ 1;
        // preact = [x_t | h_cur] @ Wcat^T + bcat  (fp32 out)
        gemm_bf<0, 0><<<tgrid(BB, GDIM), 128>>>(p_xallb + (size_t)t * BB * XD1, XD1,
                                                p_hb + (size_t)cur * BB * DD, DD, XD1,
                                                p_Wcatb, XDIM, p_bcat, p_preact, nullptr,
                                                GDIM, GDIM, XDIM);
        lstm_elem_kernel<<<(BB * DD + 255) / 256, 256>>>(cur, nxt);
        // H = relu(h2 @ WH^T); s = relu(u @ Wc^T + bc)
        hs_bf_idx<<<dim3(8, 2, 2), 128>>>(nxt, bc);
        attn_fused_kernel<<<BB, 256>>>(Wg, Wsm, wh, out_attn, t);
        // out = tanh(t1 @ Wfc^T + bfc)  (bf16 out)
        gemm_bf<2, 2><<<tgrid(BB, DD), 128>>>(p_t1b, DD, p_t1b, DD, KSINF,
                                              p_Wfcb, DD, bfc, nullptr, p_o512b, DD, DD, DD);
        // logits into d_out at [:, t, :]  (fp32 out)
        gemm_bf<0, 0><<<tgrid(BB, VV), 128>>>(p_o512b, DD, p_o512b, DD, KSINF,
                                              p_Wpb, DD, bp, out_logits + (size_t)t * VV, nullptr,
                                              (long long)TT * VV, VV, DD);
    }

    log_softmax_kernel<<<BB * TT, 256>>>(out_logits);
}

// round 6
// speedup vs baseline: 4.5042x; 2.0318x over previous
#include <cuda_runtime.h>
#include <cuda_bf16.h>
#include <math.h>
#include <stdint.h>

// Problem constants
#define BB 128
#define NN 49
#define CC 2048
#define DD 512
#define EE 512
#define VV 10000
#define TT 20
#define XD1 1024       // x = [vg | we]
#define GDIM 2560      // 4D gates + D gate-linear
#define MT (BB * TT)   // 2560 batched rows
#define KSINF (1 << 30)

typedef __nv_bfloat16 bf16;

// ---------------- device scratch ----------------
__device__ __align__(16) bf16 g_imgb[BB * NN * CC];
__device__ __align__(16) bf16 g_meanb[BB * CC];
__device__ __align__(16) bf16 g_Wbhmb[1536 * CC];
__device__ __align__(16) bf16 g_Wab[DD * CC];
__device__ __align__(16) bf16 g_Wvb[NN * DD];
__device__ __align__(16) bf16 g_Wgb[NN * DD];
__device__ __align__(16) bf16 g_Wsmb[NN * DD];
__device__ __align__(16) bf16 g_Vfb[BB * NN * DD];
__device__ __align__(16) bf16 g_xallb[MT * XD1];
__device__ __align__(16) bf16 g_Wxcatb[GDIM * XD1];
__device__ __align__(16) bf16 g_Whhcatb[GDIM * DD];
__device__ __align__(16) bf16 g_WHb[DD * DD];
__device__ __align__(16) bf16 g_Wcb[DD * DD];
__device__ __align__(16) bf16 g_Wfcb[DD * DD];
__device__ __align__(16) bf16 g_Wpb[VV * DD];
__device__ __align__(16) bf16 g_hall[(TT + 1) * BB * DD];  // slot 0 = h0, slot t+1 = h2(t)
__device__ __align__(16) bf16 g_uall[MT * DD];
__device__ __align__(16) bf16 g_Hallb[MT * DD];
__device__ __align__(16) bf16 g_sallb[MT * DD];
__device__ __align__(16) bf16 g_t1all[MT * DD];
__device__ __align__(16) bf16 g_o512all[MT * DD];
// fp32
__device__ __align__(16) float g_vghm[BB * 1536];
__device__ __align__(16) float g_zbase[BB * NN * NN];
__device__ __align__(16) float g_bbhm[1536];
__device__ __align__(16) float g_bcat[GDIM];
__device__ __align__(16) float g_xpre[(size_t)MT * GDIM];
__device__ __align__(16) float g_preact[BB * GDIM];
__device__ __align__(16) float g_m[2][BB * DD];
__device__ __align__(16) float g_gHall[MT * NN];
__device__ __align__(16) float g_sWsall[MT * NN];

__device__ __forceinline__ float sigf(float x) { return 1.0f / (1.0f + expf(-x)); }

__device__ __forceinline__ uint4 ldsm4(uint32_t addr) {
    uint4 r;
    asm volatile("ldmatrix.sync.aligned.m8n8.x4.shared.b16 {%0,%1,%2,%3}, [%4];"
                 : "=r"(r.x), "=r"(r.y), "=r"(r.z), "=r"(r.w) : "r"(addr));
    return r;
}

__device__ __forceinline__ void mma16(float* c, const uint4 a, uint32_t b0, uint32_t b1) {
    asm volatile("mma.sync.aligned.m16n8k16.row.col.f32.bf16.bf16.f32 "
        "{%0,%1,%2,%3}, {%4,%5,%6,%7}, {%8,%9}, {%0,%1,%2,%3};"
        : "+f"(c[0]), "+f"(c[1]), "+f"(c[2]), "+f"(c[3])
        : "r"(a.x), "r"(a.y), "r"(a.z), "r"(a.w), "r"(b0), "r"(b1));
}

// ============ bf16 tensor-core GEMM body ============
// C[m,n] = act( sum_k A[m,k]*W[n,k] + bias[n] + (INIT? Ci[m,n] : 0) )
// OUT: 0 = fp32 C, 2 = bf16 Cb. REMAP: out row = (m&127)*TT + (m>>7), ldc=VV.
template <int ACT, int OUT, int INIT, int REMAP>
__device__ __forceinline__ void gemm_bf_body(
    const bf16* __restrict__ A, int lda,
    const bf16* __restrict__ W, int ldw,
    const float* __restrict__ bias,
    const float* __restrict__ Ci,
    float* __restrict__ C, bf16* __restrict__ Cb,
    long long ldc, int N, int K)
{
    __shared__ __align__(16) bf16 sA[64 * 40];
    __shared__ __align__(16) bf16 sB[64 * 40];

    const int tid = threadIdx.x;
    const int lane = tid & 31, w = tid >> 5;
    const int wm = (w >> 1) * 32, wn = (w & 1) * 32;
    const int m0 = blockIdx.y * 64, n0 = blockIdx.x * 64;
    const int g = lane >> 2, q = lane & 3;
    const int grow = tid >> 1;
    const int gc0 = (tid & 1) * 2;
    const uint4 z4 = make_uint4(0, 0, 0, 0);

    const uint32_t baseA = (uint32_t)__cvta_generic_to_shared(sA);
    const uint32_t baseB = (uint32_t)__cvta_generic_to_shared(sB);
    const int rA = wm + (lane & 7) + ((lane >> 3) & 1) * 8;
    const uint32_t offA0 = baseA + (uint32_t)(rA * 40 + (lane >> 4) * 8) * 2;
    const int rB = wn + (lane & 7);
    const uint32_t offB0 = baseB + (uint32_t)(rB * 40 + (lane >> 3) * 8) * 2;

    float acc[2][4][4];
#pragma unroll
    for (int i = 0; i < 2; i++)
#pragma unroll
        for (int j = 0; j < 4; j++)
#pragma unroll
            for (int u = 0; u < 4; u++) acc[i][j][u] = 0.f;

    uint4 pa[2], pb[2];
    auto load_regs = [&](int k0) {
#pragma unroll
        for (int e = 0; e < 2; e++) {
            const int gk = k0 + (gc0 + e) * 8;
            pa[e] = *reinterpret_cast<const uint4*>(A + (size_t)(m0 + grow) * lda + gk);
            pb[e] = (n0 + grow < N)
                ? *reinterpret_cast<const uint4*>(W + (size_t)(n0 + grow) * ldw + gk)
                : z4;
        }
    };
    auto store_smem = [&]() {
#pragma unroll
        for (int e = 0; e < 2; e++) {
            *reinterpret_cast<uint4*>(&sA[grow * 40 + (gc0 + e) * 8]) = pa[e];
            *reinterpret_cast<uint4*>(&sB[grow * 40 + (gc0 + e) * 8]) = pb[e];
        }
    };

    load_regs(0);
    store_smem();

    for (int k0 = 0; k0 < K; k0 += 32) {
        __syncthreads();
        const bool more = (k0 + 32) < K;
        if (more) load_regs(k0 + 32);

        uint4 bfr[4];
#pragma unroll
        for (int j = 0; j < 4; j++) bfr[j] = ldsm4(offB0 + j * 640);
#pragma unroll
        for (int kt = 0; kt < 2; kt++) {
            uint4 af0 = ldsm4(offA0 + kt * 32);
            uint4 af1 = ldsm4(offA0 + 1280 + kt * 32);
#pragma unroll
            for (int j = 0; j < 4; j++) {
                const uint32_t b0 = kt ? bfr[j].z : bfr[j].x;
                const uint32_t b1 = kt ? bfr[j].w : bfr[j].y;
                mma16(acc[0][j], af0, b0, b1);
                mma16(acc[1][j], af1, b0, b1);
            }
        }
        if (more) {
            __syncthreads();
            store_smem();
        }
    }

    // ---- epilogue ----
#pragma unroll
    for (int i = 0; i < 2; i++) {
        const int r0 = m0 + wm + i * 16 + g;
        const long long orow0 = REMAP ? (long long)((r0 & 127) * TT + (r0 >> 7)) : (long long)r0;
        const long long orow1 = REMAP ? (long long)(((r0 + 8) & 127) * TT + ((r0 + 8) >> 7)) : (long long)(r0 + 8);
#pragma unroll
        for (int j = 0; j < 4; j++) {
            const int col = n0 + wn + j * 8 + q * 2;
            float b0v = 0.f, b1v = 0.f;
            if (bias) {
                if (col < N)     b0v = bias[col];
                if (col + 1 < N) b1v = bias[col + 1];
            }
            float v00 = acc[i][j][0] + b0v, v01 = acc[i][j][1] + b1v;
            float v10 = acc[i][j][2] + b0v, v11 = acc[i][j][3] + b1v;
            if (INIT) {
                if (col < N) {
                    v00 += Ci[(size_t)r0 * ldc + col];
                    v10 += Ci[(size_t)(r0 + 8) * ldc + col];
                }
                if (col + 1 < N) {
                    v01 += Ci[(size_t)r0 * ldc + col + 1];
                    v11 += Ci[(size_t)(r0 + 8) * ldc + col + 1];
                }
            }
            if (ACT == 1) {
                v00 = fmaxf(v00, 0.f); v01 = fmaxf(v01, 0.f);
                v10 = fmaxf(v10, 0.f); v11 = fmaxf(v11, 0.f);
            } else if (ACT == 2) {
                v00 = tanhf(v00); v01 = tanhf(v01);
                v10 = tanhf(v10); v11 = tanhf(v11);
            }
            if (col < N) {
                if (OUT == 0) {
                    C[orow0 * ldc + col] = v00;
                    C[orow1 * ldc + col] = v10;
                } else {
                    Cb[orow0 * ldc + col] = __float2bfloat16(v00);
                    Cb[orow1 * ldc + col] = __float2bfloat16(v10);
                }
            }
            if (col + 1 < N) {
                if (OUT == 0) {
                    C[orow0 * ldc + col + 1] = v01;
                    C[orow1 * ldc + col + 1] = v11;
                } else {
                    Cb[orow0 * ldc + col + 1] = __float2bfloat16(v01);
                    Cb[orow1 * ldc + col + 1] = __float2bfloat16(v11);
                }
            }
        }
    }
}

template <int ACT, int OUT, int INIT, int REMAP>
__global__ __launch_bounds__(128) void gemm_bf(
    const bf16* __restrict__ A, int lda,
    const bf16* __restrict__ W, int ldw,
    const float* __restrict__ bias,
    const float* __restrict__ Ci,
    float* __restrict__ C, bf16* __restrict__ Cb, long long ldc, int N, int K)
{
    gemm_bf_body<ACT, OUT, INIT, REMAP>(A, lda, W, ldw, bias, Ci, C, Cb, ldc, N, K);
}

// batched H & s (z selects), M = 2560, bf16 outputs
__global__ __launch_bounds__(128) void hs_batched(const float* __restrict__ bc)
{
    if (blockIdx.z == 0)
        gemm_bf_body<1, 2, 0, 0>(g_hall + BB * DD, DD, g_WHb, DD, nullptr, nullptr,
                                 nullptr, g_Hallb, DD, DD, DD);
    else
        gemm_bf_body<1, 2, 0, 0>(g_uall, DD, g_Wcb, DD, bc, nullptr,
                                 nullptr, g_sallb, DD, DD, DD);
}

// batched gH & sWs (z selects), M = 2560, N = 49, fp32 outputs
__global__ __launch_bounds__(128) void ghsw_batched()
{
    if (blockIdx.z == 0)
        gemm_bf_body<0, 0, 0, 0>(g_Hallb, DD, g_Wgb, DD, nullptr, nullptr,
                                 g_gHall, nullptr, NN, NN, DD);
    else
        gemm_bf_body<0, 0, 0, 0>(g_sallb, DD, g_Wsmb, DD, nullptr, nullptr,
                                 g_sWsall, nullptr, NN, NN, DD);
}

// ---------------- conversion / setup kernels ----------------
__global__ void cvt_bf16_kernel(const float* __restrict__ in, bf16* __restrict__ out, int n4)
{
    int idx = blockIdx.x * blockDim.x + threadIdx.x;
    if (idx >= n4) return;
    float4 v = reinterpret_cast<const float4*>(in)[idx];
    reinterpret_cast<__nv_bfloat162*>(out)[idx * 2]     = __floats2bfloat162_rn(v.x, v.y);
    reinterpret_cast<__nv_bfloat162*>(out)[idx * 2 + 1] = __floats2bfloat162_rn(v.z, v.w);
}

__global__ void mean_kernel(const float* __restrict__ img)
{
    int idx = blockIdx.x * blockDim.x + threadIdx.x;
    if (idx >= BB * CC) return;
    int b = idx / CC, c = idx % CC;
    const float* p = img + (size_t)b * NN * CC + c;
    float s = 0.f;
#pragma unroll 7
    for (int n = 0; n < NN; n++) s += p[(size_t)n * CC];
    g_meanb[idx] = __float2bfloat16(s * (1.0f / NN));
}

__global__ void build_wbhm_kernel(const float* __restrict__ Wb, const float* __restrict__ Whi,
                                  const float* __restrict__ Wmi,
                                  const float* __restrict__ bb, const float* __restrict__ bhi,
                                  const float* __restrict__ bmi)
{
    int idx = blockIdx.x * blockDim.x + threadIdx.x;
    if (idx >= 1536 * CC) return;
    int r = idx / CC, c = idx % CC;
    float v;
    if (r < 512)       v = Wb[(size_t)r * CC + c];
    else if (r < 1024) v = Whi[(size_t)(r - 512) * CC + c];
    else               v = Wmi[(size_t)(r - 1024) * CC + c];
    g_Wbhmb[idx] = __float2bfloat16(v);
    if (c == 0) g_bbhm[r] = (r < 512) ? bb[r] : (r < 1024 ? bhi[r - 512] : bmi[r - 1024]);
}

__global__ void build_wxcat_kernel(const float* __restrict__ Wih, const float* __restrict__ Wx,
                                   const float* __restrict__ bih, const float* __restrict__ bhh)
{
    int idx = blockIdx.x * blockDim.x + threadIdx.x;
    if (idx >= GDIM * XD1) return;
    int r = idx / XD1, c = idx % XD1;
    float v = (r < 2048) ? Wih[(size_t)r * XD1 + c] : Wx[(size_t)(r - 2048) * XD1 + c];
    g_Wxcatb[idx] = __float2bfloat16(v);
    if (c == 0) g_bcat[r] = (r < 2048) ? (bih[r] + bhh[r]) : 0.f;
}

__global__ void build_whhcat_kernel(const float* __restrict__ Whh, const float* __restrict__ Wh2)
{
    int idx = blockIdx.x * blockDim.x + threadIdx.x;
    if (idx >= GDIM * DD) return;
    int r = idx / DD, c = idx % DD;
    float v = (r < 2048) ? Whh[(size_t)r * DD + c] : Wh2[(size_t)(r - 2048) * DD + c];
    g_Whhcatb[idx] = __float2bfloat16(v);
}

__global__ void hm_init_kernel()
{
    int idx = blockIdx.x * blockDim.x + threadIdx.x;
    if (idx >= BB * DD) return;
    int b = idx >> 9, d = idx & 511;
    g_hall[idx] = __float2bfloat16(g_vghm[b * 1536 + 512 + d]);
    g_m[0][idx] = g_vghm[b * 1536 + 1024 + d];
}

__global__ void xall_init_kernel(const float* __restrict__ emb, const int* __restrict__ target)
{
    int idx = blockIdx.x * blockDim.x + threadIdx.x;
    if (idx >= MT * XD1) return;
    int j = idx % XD1;
    int tb = idx / XD1;
    int b = tb % BB;
    int t = tb / BB;
    float v;
    if (j < 512) v = g_vghm[b * 1536 + j];
    else if (t == 0) v = 0.f;
    else {
        int tok = target[b * TT + t - 1];
        v = emb[(size_t)tok * EE + (j - 512)];
    }
    g_xallb[((size_t)t * BB + b) * XD1 + j] = __float2bfloat16(v);
}

// LSTM nonlinearity; writes hall slot t+1 and uall slot t
__global__ void lstm_elem_kernel(int t)
{
    int idx = blockIdx.x * blockDim.x + threadIdx.x;
    if (idx >= BB * DD) return;
    int b = idx >> 9, d = idx & 511;
    int cur = t & 1, nxt = cur ^ 1;
    const float* p = g_preact + (size_t)b * GDIM;
    float gi = p[d], gf = p[512 + d], gg = p[1024 + d], go = p[1536 + d], gl = p[2048 + d];
    float m2 = sigf(gf) * g_m[cur][idx] + sigf(gi) * tanhf(gg);
    float tm2 = tanhf(m2);
    g_m[nxt][idx] = m2;
    g_hall[(size_t)(t + 1) * BB * DD + idx] = __float2bfloat16(sigf(go) * tm2);
    g_uall[(size_t)t * BB * DD + idx] = __float2bfloat16(sigf(gl) * tm2);
}

// batched attention: one block per (t,b); z, z2, softmax(50), attn out, ctx, t1
__global__ void attn_fused_kernel(const float* __restrict__ wh, float* __restrict__ attn_out)
{
    const int r = blockIdx.x;            // t*128 + b
    const int t = r >> 7, b = r & 127;
    __shared__ float gHs[49], sWss[49], zsh[50], wsh[49];
    int tid = threadIdx.x;  // 128

    if (tid < 49) {
        gHs[tid] = g_gHall[r * 49 + tid];
        sWss[tid] = g_sWsall[r * 49 + tid];
        wsh[tid] = wh[tid];
    }
    __syncthreads();

    if (tid < 49) {
        const float* zb = g_zbase + ((size_t)b * 49 + tid) * 49;
        float acc = 0.f;
#pragma unroll 7
        for (int k = 0; k < 49; k++) acc += tanhf(zb[k] + gHs[k]) * wsh[k];
        zsh[tid] = acc;
    } else if (tid == 49) {
        float acc = 0.f;
#pragma unroll 7
        for (int k = 0; k < 49; k++) acc += tanhf(sWss[k] + gHs[k]) * wsh[k];
        zsh[49] = acc;
    }
    __syncthreads();

    if (tid == 0) {
        float mx = -1e30f;
        for (int i = 0; i < 50; i++) mx = fmaxf(mx, zsh[i]);
        float sum = 0.f;
        for (int i = 0; i < 50; i++) { zsh[i] = expf(zsh[i] - mx); sum += zsh[i]; }
        float inv = 1.f / sum;
        for (int i = 0; i < 50; i++) zsh[i] *= inv;
    }
    __syncthreads();

    if (tid < 49) attn_out[((size_t)b * TT + t) * 49 + tid] = zsh[tid];

    const float a50 = zsh[49];
    const bf16* srow = g_sallb + (size_t)r * 512;
    const bf16* Hrow = g_Hallb + (size_t)r * 512;
#pragma unroll
    for (int e = 0; e < 4; e++) {
        int d = tid + e * 128;
        float acc = a50 * __bfloat162float(srow[d]);
#pragma unroll 7
        for (int n = 0; n < 49; n++)
            acc = fmaf(zsh[n], __bfloat162float(g_Vfb[((size_t)b * 49 + n) * 512 + d]), acc);
        g_t1all[(size_t)r * 512 + d] = __float2bfloat16(__bfloat162float(Hrow[d]) + acc);
    }
}

__global__ void log_softmax_kernel(float* __restrict__ logits)
{
    int row = blockIdx.x;
    float* x = logits + (size_t)row * VV;
    __shared__ float red[256];
    int tid = threadIdx.x;
    float mx = -1e30f;
    for (int i = tid; i < VV; i += 256) mx = fmaxf(mx, x[i]);
    red[tid] = mx; __syncthreads();
    for (int s = 128; s; s >>= 1) { if (tid < s) red[tid] = fmaxf(red[tid], red[tid + s]); __syncthreads(); }
    mx = red[0];
    __syncthreads();
    float sum = 0.f;
    for (int i = tid; i < VV; i += 256) sum += expf(x[i] - mx);
    red[tid] = sum; __syncthreads();
    for (int s = 128; s; s >>= 1) { if (tid < s) red[tid] += red[tid + s]; __syncthreads(); }
    float lse = mx + logf(red[0]);
    for (int i = tid; i < VV; i += 256) x[i] -= lse;
}

// ---------------- host ----------------
static inline dim3 tgrid(int M, int N) { return dim3((N + 63) / 64, (M + 63) / 64); }

extern "C" void kernel_launch(void* const* d_in, const int* in_sizes, int n_in,
                              void* d_out, int out_size)
{
    const float* img    = (const float*)d_in[0];
    const int*   target = (const int*)d_in[1];
    const float* emb    = (const float*)d_in[2];
    const float* Wa  = (const float*)d_in[3];  const float* ba  = (const float*)d_in[4];
    const float* Wb  = (const float*)d_in[5];  const float* bb  = (const float*)d_in[6];
    const float* Whi = (const float*)d_in[7];  const float* bhi = (const float*)d_in[8];
    const float* Wmi = (const float*)d_in[9];  const float* bmi = (const float*)d_in[10];
    const float* Wih = (const float*)d_in[11]; const float* bih = (const float*)d_in[12];
    const float* Whh = (const float*)d_in[13]; const float* bhh = (const float*)d_in[14];
    const float* Wv  = (const float*)d_in[15];
    const float* Wg  = (const float*)d_in[16];
    const float* wh  = (const float*)d_in[17];
    const float* WH  = (const float*)d_in[18];
    const float* Wx  = (const float*)d_in[19];
    const float* Wh2 = (const float*)d_in[20];
    const float* Wsm = (const float*)d_in[21];
    const float* Wc  = (const float*)d_in[22]; const float* bc  = (const float*)d_in[23];
    const float* Wfc = (const float*)d_in[24]; const float* bfc = (const float*)d_in[25];
    const float* Wp  = (const float*)d_in[26]; const float* bp  = (const float*)d_in[27];

    float* out_logits = (float*)d_out;                               // [B,T,VOC]
    float* out_attn   = (float*)d_out + (size_t)BB * TT * VV;        // [B,T,N]

    bf16 *p_imgb, *p_meanb, *p_Wbhmb, *p_Wab, *p_Wvb, *p_Wgb, *p_Wsmb, *p_Vfb, *p_xallb;
    bf16 *p_Wxcatb, *p_Whhcatb, *p_WHb, *p_Wcb, *p_Wfcb, *p_Wpb, *p_hall, *p_t1all, *p_o512all;
    float *p_vghm, *p_zbase, *p_bbhm, *p_bcat, *p_xpre, *p_preact;
    cudaGetSymbolAddress((void**)&p_imgb,   g_imgb);
    cudaGetSymbolAddress((void**)&p_meanb,  g_meanb);
    cudaGetSymbolAddress((void**)&p_Wbhmb,  g_Wbhmb);
    cudaGetSymbolAddress((void**)&p_Wab,    g_Wab);
    cudaGetSymbolAddress((void**)&p_Wvb,    g_Wvb);
    cudaGetSymbolAddress((void**)&p_Wgb,    g_Wgb);
    cudaGetSymbolAddress((void**)&p_Wsmb,   g_Wsmb);
    cudaGetSymbolAddress((void**)&p_Vfb,    g_Vfb);
    cudaGetSymbolAddress((void**)&p_xallb,  g_xallb);
    cudaGetSymbolAddress((void**)&p_Wxcatb, g_Wxcatb);
    cudaGetSymbolAddress((void**)&p_Whhcatb,g_Whhcatb);
    cudaGetSymbolAddress((void**)&p_WHb,    g_WHb);
    cudaGetSymbolAddress((void**)&p_Wcb,    g_Wcb);
    cudaGetSymbolAddress((void**)&p_Wfcb,   g_Wfcb);
    cudaGetSymbolAddress((void**)&p_Wpb,    g_Wpb);
    cudaGetSymbolAddress((void**)&p_hall,   g_hall);
    cudaGetSymbolAddress((void**)&p_t1all,  g_t1all);
    cudaGetSymbolAddress((void**)&p_o512all,g_o512all);
    cudaGetSymbolAddress((void**)&p_vghm,   g_vghm);
    cudaGetSymbolAddress((void**)&p_zbase,  g_zbase);
    cudaGetSymbolAddress((void**)&p_bbhm,   g_bbhm);
    cudaGetSymbolAddress((void**)&p_bcat,   g_bcat);
    cudaGetSymbolAddress((void**)&p_xpre,   g_xpre);
    cudaGetSymbolAddress((void**)&p_preact, g_preact);

    auto cvt = [&](const float* in, bf16* out, int n) {
        cvt_bf16_kernel<<<(n / 4 + 255) / 256, 256>>>(in, out, n / 4);
    };
    // ---- precompute ----
    cvt(img, p_imgb, BB * NN * CC);
    cvt(Wa,  p_Wab,  DD * CC);
    cvt(Wv,  p_Wvb,  NN * DD);
    cvt(Wg,  p_Wgb,  NN * DD);
    cvt(Wsm, p_Wsmb, NN * DD);
    cvt(WH,  p_WHb,  DD * DD);
    cvt(Wc,  p_Wcb,  DD * DD);
    cvt(Wfc, p_Wfcb, DD * DD);
    cvt(Wp,  p_Wpb,  VV * DD);
    build_wbhm_kernel<<<(1536 * CC + 255) / 256, 256>>>(Wb, Whi, Wmi, bb, bhi, bmi);
    build_wxcat_kernel<<<(GDIM * XD1 + 255) / 256, 256>>>(Wih, Wx, bih, bhh);
    build_whhcat_kernel<<<(GDIM * DD + 255) / 256, 256>>>(Whh, Wh2);
    mean_kernel<<<(BB * CC + 255) / 256, 256>>>(img);

    // [vg|h0|m0] = relu(mean @ Wbhm^T + bbhm)
    gemm_bf<1, 0, 0, 0><<<tgrid(BB, 1536), 128>>>(p_meanb, CC, p_Wbhmb, CC, p_bbhm,
                                                  nullptr, p_vghm, nullptr, 1536, 1536, CC);
    hm_init_kernel<<<(BB * DD + 255) / 256, 256>>>();
    // Vf (bf16)
    gemm_bf<1, 2, 0, 0><<<tgrid(BB * NN, DD), 128>>>(p_imgb, CC, p_Wab, CC, ba,
                                                     nullptr, nullptr, p_Vfb, DD, DD, CC);
    // zbase (fp32)
    gemm_bf<0, 0, 0, 0><<<tgrid(BB * NN, NN), 128>>>(p_Vfb, DD, p_Wvb, DD, nullptr,
                                                     nullptr, p_zbase, nullptr, NN, NN, DD);
    xall_init_kernel<<<(MT * XD1 + 255) / 256, 256>>>(emb, target);
    // xpre = xall @ Wxcat^T + bcat  (fp32, all timesteps)
    gemm_bf<0, 0, 0, 0><<<tgrid(MT, GDIM), 128>>>(p_xallb, XD1, p_Wxcatb, XD1, p_bcat,
                                                  nullptr, p_xpre, nullptr, GDIM, GDIM, XD1);

    // ---- serial recurrence: only preact(h) + lstm ----
    for (int t = 0; t < TT; t++) {
        gemm_bf<0, 0, 1, 0><<<tgrid(BB, GDIM), 128>>>(
            p_hall + (size_t)t * BB * DD, DD, p_Whhcatb, DD, nullptr,
            p_xpre + (size_t)t * BB * GDIM, p_preact, nullptr, GDIM, GDIM, DD);
        lstm_elem_kernel<<<(BB * DD + 255) / 256, 256>>>(t);
    }

    // ---- batched tail over all timesteps ----
    hs_batched<<<dim3(8, MT / 64, 2), 128>>>(bc);
    ghsw_batched<<<dim3(1, MT / 64, 2), 128>>>();
    attn_fused_kernel<<<MT, 128>>>(wh, out_attn);
    gemm_bf<2, 2, 0, 0><<<tgrid(MT, DD), 128>>>(p_t1all, DD, p_Wfcb, DD, bfc,
                                                nullptr, nullptr, p_o512all, DD, DD, DD);
    gemm_bf<0, 0, 0, 1><<<tgrid(MT, VV), 128>>>(p_o512all, DD, p_Wpb, DD, bp,
                                                nullptr, out_logits, nullptr, VV, VV, DD);
    log_softmax_kernel<<<MT, 256>>>(out_logits);
}